// round 1
// baseline (speedup 1.0000x reference)
#include <cuda_runtime.h>

#define SQ   2048
#define BB   4
#define DIM  1024
#define NH   16
#define NDQK 20
#define NDV  64
#define DLQ  256
#define DLKV 128
#define NTOK (BB*SQ)   /* 8192 */

// ---------------- scratch (static device globals; no allocation) ----------------
__device__ float g_qraw[NTOK*DLQ];
__device__ float g_kraw[NTOK*DLKV];
__device__ float g_qlat[NTOK*DLQ];
__device__ float g_kvn [NTOK*DLKV];
__device__ float g_qkv [(size_t)NTOK*NH*DLKV];   // 64 MB
__device__ float g_vlat[(size_t)NTOK*NH*DLKV];   // 64 MB
__device__ float g_wc  [NH*DLKV*DLQ];            // absorbed q->latent weight [2048][256]
__device__ float g_biasc[NH*DLKV];
__device__ float g_wo2 [DIM*NH*DLKV];            // absorbed v->out weight   [1024][2048]

// ---------------- weight absorption kernels (tiny) ----------------
__global__ void prep_wc_kernel(const float* __restrict__ wq_b_w,
                               const float* __restrict__ wq_b_b,
                               const float* __restrict__ wkv_b_w,
                               float* __restrict__ wc, float* __restrict__ biasc) {
    int hc = blockIdx.x;            // 0..2047
    int h  = hc >> 7;
    int c  = hc & 127;
    int l  = threadIdx.x;           // 0..255
    float acc = 0.f, accb = 0.f;
    #pragma unroll
    for (int q = 0; q < NDQK; q++) {
        float kb = wkv_b_w[(size_t)(h*(NDQK+NDV) + q)*DLKV + c];
        acc  = fmaf(kb, wq_b_w[(size_t)(h*NDQK + q)*DLQ + l], acc);
        accb = fmaf(kb, wq_b_b[h*NDQK + q], accb);
    }
    wc[(size_t)hc*DLQ + l] = acc;
    if (l == 0) biasc[hc] = accb;
}

__global__ void prep_wo2_kernel(const float* __restrict__ wo_w,
                                const float* __restrict__ wkv_b_w,
                                float* __restrict__ wo2) {
    int d = blockIdx.x;             // 0..1023
    int h = blockIdx.y;             // 0..15
    int c = threadIdx.x;            // 0..127
    float acc = 0.f;
    #pragma unroll 8
    for (int v = 0; v < NDV; v++)
        acc = fmaf(wo_w[(size_t)d*(NH*NDV) + h*NDV + v],
                   wkv_b_w[(size_t)(h*(NDQK+NDV) + NDQK + v)*DLKV + c], acc);
    wo2[(size_t)d*(NH*DLKV) + h*DLKV + c] = acc;
}

// ---------------- RMSNorm (one block per row) ----------------
__global__ void rms_kernel(const float* __restrict__ in, const float* __restrict__ w,
                           float* __restrict__ out, int N) {
    int row = blockIdx.x;
    const float* x = in + (size_t)row * N;
    float ss = 0.f;
    for (int i = threadIdx.x; i < N; i += 128) { float v = x[i]; ss = fmaf(v, v, ss); }
    ss += __shfl_xor_sync(0xffffffffu, ss, 16);
    ss += __shfl_xor_sync(0xffffffffu, ss, 8);
    ss += __shfl_xor_sync(0xffffffffu, ss, 4);
    ss += __shfl_xor_sync(0xffffffffu, ss, 2);
    ss += __shfl_xor_sync(0xffffffffu, ss, 1);
    __shared__ float red[4];
    if ((threadIdx.x & 31) == 0) red[threadIdx.x >> 5] = ss;
    __syncthreads();
    float tot = red[0] + red[1] + red[2] + red[3];
    float r = rsqrtf(tot / (float)N + 1e-6f);
    for (int i = threadIdx.x; i < N; i += 128)
        out[(size_t)row*N + i] = x[i] * r * w[i];
}

// ---------------- SGEMM: C[M,N] = A[M,K] @ B[N,K]^T + bias[N] ----------------
// 128x128 tile, 8x8 micro, BK=16, 256 threads.
__global__ __launch_bounds__(256) void sgemm_nt_bias(
    const float* __restrict__ A, const float* __restrict__ B,
    const float* __restrict__ bias, float* __restrict__ C,
    int M, int N, int K)
{
    __shared__ float sA[16][132];
    __shared__ float sB[16][132];
    const int mt = blockIdx.x * 128;
    const int nt = blockIdx.y * 128;
    const int tid = threadIdx.x;
    const int ty = tid >> 4, tx = tid & 15;

    float acc[8][8];
    #pragma unroll
    for (int i = 0; i < 8; i++)
        #pragma unroll
        for (int j = 0; j < 8; j++) acc[i][j] = 0.f;

    for (int k0 = 0; k0 < K; k0 += 16) {
        __syncthreads();
        #pragma unroll
        for (int s = 0; s < 2; s++) {
            int f = tid + s * 256;          // 0..511
            int r  = f >> 2;                // 0..127
            int kk = (f & 3) << 2;          // 0,4,8,12
            float4 av = *(const float4*)&A[(size_t)(mt + r)*K + k0 + kk];
            sA[kk+0][r] = av.x; sA[kk+1][r] = av.y; sA[kk+2][r] = av.z; sA[kk+3][r] = av.w;
            float4 bv = *(const float4*)&B[(size_t)(nt + r)*K + k0 + kk];
            sB[kk+0][r] = bv.x; sB[kk+1][r] = bv.y; sB[kk+2][r] = bv.z; sB[kk+3][r] = bv.w;
        }
        __syncthreads();
        #pragma unroll
        for (int kk = 0; kk < 16; kk++) {
            float a[8], b[8];
            *(float4*)&a[0] = *(const float4*)&sA[kk][ty*8];
            *(float4*)&a[4] = *(const float4*)&sA[kk][ty*8 + 4];
            *(float4*)&b[0] = *(const float4*)&sB[kk][tx*8];
            *(float4*)&b[4] = *(const float4*)&sB[kk][tx*8 + 4];
            #pragma unroll
            for (int i = 0; i < 8; i++)
                #pragma unroll
                for (int j = 0; j < 8; j++) acc[i][j] = fmaf(a[i], b[j], acc[i][j]);
        }
    }
    #pragma unroll
    for (int i = 0; i < 8; i++) {
        size_t row = (size_t)(mt + ty*8 + i);
        #pragma unroll
        for (int j = 0; j < 8; j++) acc[i][j] += bias[nt + tx*8 + j];
        *(float4*)&C[row*N + nt + tx*8]     = make_float4(acc[i][0], acc[i][1], acc[i][2], acc[i][3]);
        *(float4*)&C[row*N + nt + tx*8 + 4] = make_float4(acc[i][4], acc[i][5], acc[i][6], acc[i][7]);
    }
}

// ---------------- Flash attention in latent space ----------------
// Q = g_qkv[b,:,h,:], K = V = g_kvn[b]. One block per (qtile=64, h, b).
// smem: QT[128][64] | KT[128][64] | V[64][128] | P[64][64]  = 112 KB
__global__ __launch_bounds__(256) void attn_kernel(
    const float* __restrict__ qkv, const float* __restrict__ kvn,
    float* __restrict__ vlat)
{
    extern __shared__ float sm[];
    float* sQ = sm;            // [128][64] (k-major)
    float* sK = sm + 8192;     // [128][64] (k-major)
    float* sV = sm + 16384;    // [64][128] (row-major)
    float* sP = sm + 24576;    // [64][64]

    const int qt = blockIdx.x, h = blockIdx.y, b = blockIdx.z;
    const int tid = threadIdx.x;
    const int ty = tid >> 4, tx = tid & 15;
    const int q0 = qt * 64;
    const int r0 = ty * 4, c0 = tx * 4, oc0 = tx * 8;
    const float scale = 0.2236067977499790f;   // 1/sqrt(20)

    // load Q tile transposed
    for (int idx = tid; idx < 2048; idx += 256) {
        int q = idx & 63, kc = idx >> 6;
        float4 v = *(const float4*)&qkv[((size_t)((b*SQ + q0 + q)*NH + h) << 7) + (kc << 2)];
        sQ[(kc*4+0)*64 + q] = v.x; sQ[(kc*4+1)*64 + q] = v.y;
        sQ[(kc*4+2)*64 + q] = v.z; sQ[(kc*4+3)*64 + q] = v.w;
    }

    float o[4][8];
    float m[4], l[4];
    #pragma unroll
    for (int i = 0; i < 4; i++) {
        m[i] = -1e30f; l[i] = 0.f;
        #pragma unroll
        for (int j = 0; j < 8; j++) o[i][j] = 0.f;
    }

    for (int kt = 0; kt <= qt; ++kt) {
        const int k0 = kt * 64;
        __syncthreads();   // prior PV done before overwriting K/V (also fences Q load at kt=0... Q is fenced by next sync)
        for (int idx = tid; idx < 2048; idx += 256) {
            int ky = idx & 63, kc = idx >> 6;
            float4 v = *(const float4*)&kvn[((size_t)(b*SQ + k0 + ky) << 7) + (kc << 2)];
            sK[(kc*4+0)*64 + ky] = v.x; sK[(kc*4+1)*64 + ky] = v.y;
            sK[(kc*4+2)*64 + ky] = v.z; sK[(kc*4+3)*64 + ky] = v.w;
            *(float4*)&sV[ky*128 + kc*4] = v;
        }
        __syncthreads();

        // S = Q @ K^T (4x4 micro-tile per thread)
        float s[4][4];
        #pragma unroll
        for (int i = 0; i < 4; i++)
            #pragma unroll
            for (int j = 0; j < 4; j++) s[i][j] = 0.f;
        #pragma unroll 8
        for (int k = 0; k < 128; k++) {
            float qa[4], ka[4];
            *(float4*)qa = *(const float4*)&sQ[k*64 + r0];
            *(float4*)ka = *(const float4*)&sK[k*64 + c0];
            #pragma unroll
            for (int i = 0; i < 4; i++)
                #pragma unroll
                for (int j = 0; j < 4; j++) s[i][j] = fmaf(qa[i], ka[j], s[i][j]);
        }

        const bool diag = (kt == qt);
        #pragma unroll
        for (int i = 0; i < 4; i++) {
            const int gq = q0 + r0 + i;
            float mm = -1e30f;
            #pragma unroll
            for (int j = 0; j < 4; j++) {
                float sv = s[i][j] * scale;
                if (diag && (k0 + c0 + j > gq)) sv = -1e30f;
                s[i][j] = sv;
                mm = fmaxf(mm, sv);
            }
            mm = fmaxf(mm, __shfl_xor_sync(0xffffffffu, mm, 1));
            mm = fmaxf(mm, __shfl_xor_sync(0xffffffffu, mm, 2));
            mm = fmaxf(mm, __shfl_xor_sync(0xffffffffu, mm, 4));
            mm = fmaxf(mm, __shfl_xor_sync(0xffffffffu, mm, 8));
            float mn = fmaxf(m[i], mm);
            float alpha = __expf(m[i] - mn);
            float ls = 0.f;
            #pragma unroll
            for (int j = 0; j < 4; j++) { float p = __expf(s[i][j] - mn); s[i][j] = p; ls += p; }
            ls += __shfl_xor_sync(0xffffffffu, ls, 1);
            ls += __shfl_xor_sync(0xffffffffu, ls, 2);
            ls += __shfl_xor_sync(0xffffffffu, ls, 4);
            ls += __shfl_xor_sync(0xffffffffu, ls, 8);
            l[i] = l[i]*alpha + ls;
            m[i] = mn;
            #pragma unroll
            for (int j = 0; j < 8; j++) o[i][j] *= alpha;
            *(float4*)&sP[(r0+i)*64 + c0] = make_float4(s[i][0], s[i][1], s[i][2], s[i][3]);
        }
        __syncthreads();

        // O += P @ V (4 rows x 8 cols per thread; P reads are broadcast)
        #pragma unroll 4
        for (int kk = 0; kk < 64; kk++) {
            float pv[4];
            pv[0] = sP[(r0+0)*64 + kk];
            pv[1] = sP[(r0+1)*64 + kk];
            pv[2] = sP[(r0+2)*64 + kk];
            pv[3] = sP[(r0+3)*64 + kk];
            float vv[8];
            *(float4*)&vv[0] = *(const float4*)&sV[kk*128 + oc0];
            *(float4*)&vv[4] = *(const float4*)&sV[kk*128 + oc0 + 4];
            #pragma unroll
            for (int i = 0; i < 4; i++)
                #pragma unroll
                for (int j = 0; j < 8; j++) o[i][j] = fmaf(pv[i], vv[j], o[i][j]);
        }
    }

    #pragma unroll
    for (int i = 0; i < 4; i++) {
        float inv = 1.f / l[i];
        int gq = q0 + r0 + i;
        size_t base = ((size_t)((b*SQ + gq)*NH + h) << 7) + oc0;
        *(float4*)&vlat[base]     = make_float4(o[i][0]*inv, o[i][1]*inv, o[i][2]*inv, o[i][3]*inv);
        *(float4*)&vlat[base + 4] = make_float4(o[i][4]*inv, o[i][5]*inv, o[i][6]*inv, o[i][7]*inv);
    }
}

// ---------------- launch ----------------
extern "C" void kernel_launch(void* const* d_in, const int* in_sizes, int n_in,
                              void* d_out, int out_size)
{
    const float* h_ptr     = (const float*)d_in[0];
    // d_in[1] = mask (causal tril) — handled analytically in attn_kernel
    const float* wq_a_w    = (const float*)d_in[2];
    const float* wq_a_b    = (const float*)d_in[3];
    const float* q_norm_w  = (const float*)d_in[4];
    const float* wq_b_w    = (const float*)d_in[5];
    const float* wq_b_b    = (const float*)d_in[6];
    const float* wkv_a_w   = (const float*)d_in[7];
    const float* wkv_a_b   = (const float*)d_in[8];
    const float* kv_norm_w = (const float*)d_in[9];
    const float* wkv_b_w   = (const float*)d_in[10];
    const float* wo_w      = (const float*)d_in[11];
    const float* wo_b      = (const float*)d_in[12];
    float* out = (float*)d_out;

    float *qraw, *kraw, *qlat, *kvn, *qkv, *vlat, *wc, *biasc, *wo2;
    cudaGetSymbolAddress((void**)&qraw,  g_qraw);
    cudaGetSymbolAddress((void**)&kraw,  g_kraw);
    cudaGetSymbolAddress((void**)&qlat,  g_qlat);
    cudaGetSymbolAddress((void**)&kvn,   g_kvn);
    cudaGetSymbolAddress((void**)&qkv,   g_qkv);
    cudaGetSymbolAddress((void**)&vlat,  g_vlat);
    cudaGetSymbolAddress((void**)&wc,    g_wc);
    cudaGetSymbolAddress((void**)&biasc, g_biasc);
    cudaGetSymbolAddress((void**)&wo2,   g_wo2);

    cudaFuncSetAttribute(attn_kernel, cudaFuncAttributeMaxDynamicSharedMemorySize, 114688);

    // weight absorption (cheap, recomputed every call for determinism)
    prep_wc_kernel<<<NH*DLKV, DLQ>>>(wq_b_w, wq_b_b, wkv_b_w, wc, biasc);
    prep_wo2_kernel<<<dim3(DIM, NH), DLKV>>>(wo_w, wkv_b_w, wo2);

    // latent projections + RMSNorm
    sgemm_nt_bias<<<dim3(NTOK/128, DLQ/128),  256>>>(h_ptr, wq_a_w,  wq_a_b,  qraw, NTOK, DLQ,  DIM);
    sgemm_nt_bias<<<dim3(NTOK/128, DLKV/128), 256>>>(h_ptr, wkv_a_w, wkv_a_b, kraw, NTOK, DLKV, DIM);
    rms_kernel<<<NTOK, 128>>>(qraw, q_norm_w,  qlat, DLQ);
    rms_kernel<<<NTOK, 128>>>(kraw, kv_norm_w, kvn,  DLKV);

    // absorbed q -> latent-kv space: [8192,256] x [2048,256]^T
    sgemm_nt_bias<<<dim3(NTOK/128, (NH*DLKV)/128), 256>>>(qlat, wc, biasc, qkv, NTOK, NH*DLKV, DLQ);

    // flash attention in latent space
    attn_kernel<<<dim3(SQ/64, NH, BB), 256, 114688>>>(qkv, kvn, vlat);

    // absorbed v -> output: [8192,2048] x [1024,2048]^T + wo_b
    sgemm_nt_bias<<<dim3(NTOK/128, DIM/128), 256>>>(vlat, wo2, wo_b, out, NTOK, DIM, NH*DLKV);
}

// round 2
// speedup vs baseline: 1.0043x; 1.0043x over previous
#include <cuda_runtime.h>

#define SQ   2048
#define BB   4
#define DIM  1024
#define NH   16
#define NDQK 20
#define NDV  64
#define DLQ  256
#define DLKV 128
#define NTOK (BB*SQ)   /* 8192 */

// ---------------- scratch (static device globals; no allocation) ----------------
__device__ float g_qraw[NTOK*DLQ];
__device__ float g_kraw[NTOK*DLKV];
__device__ float g_qlat[NTOK*DLQ];
__device__ float g_kvn [NTOK*DLKV];
__device__ float g_qkv [(size_t)NTOK*NH*DLKV];   // 64 MB
__device__ float g_vlat[(size_t)NTOK*NH*DLKV];   // 64 MB
__device__ float g_wc  [NH*DLKV*DLQ];            // absorbed q->latent weight [2048][256]
__device__ float g_biasc[NH*DLKV];
__device__ float g_wo2 [DIM*NH*DLKV];            // absorbed v->out weight   [1024][2048]

// ---------------- weight absorption kernels (tiny) ----------------
__global__ void prep_wc_kernel(const float* __restrict__ wq_b_w,
                               const float* __restrict__ wq_b_b,
                               const float* __restrict__ wkv_b_w,
                               float* __restrict__ wc, float* __restrict__ biasc) {
    int hc = blockIdx.x;            // 0..2047
    int h  = hc >> 7;
    int c  = hc & 127;
    int l  = threadIdx.x;           // 0..255
    float acc = 0.f, accb = 0.f;
    #pragma unroll
    for (int q = 0; q < NDQK; q++) {
        float kb = wkv_b_w[(size_t)(h*(NDQK+NDV) + q)*DLKV + c];
        acc  = fmaf(kb, wq_b_w[(size_t)(h*NDQK + q)*DLQ + l], acc);
        accb = fmaf(kb, wq_b_b[h*NDQK + q], accb);
    }
    wc[(size_t)hc*DLQ + l] = acc;
    if (l == 0) biasc[hc] = accb;
}

__global__ void prep_wo2_kernel(const float* __restrict__ wo_w,
                                const float* __restrict__ wkv_b_w,
                                float* __restrict__ wo2) {
    int d = blockIdx.x;             // 0..1023
    int h = blockIdx.y;             // 0..15
    int c = threadIdx.x;            // 0..127
    float acc = 0.f;
    #pragma unroll 8
    for (int v = 0; v < NDV; v++)
        acc = fmaf(wo_w[(size_t)d*(NH*NDV) + h*NDV + v],
                   wkv_b_w[(size_t)(h*(NDQK+NDV) + NDQK + v)*DLKV + c], acc);
    wo2[(size_t)d*(NH*DLKV) + h*DLKV + c] = acc;
}

// ---------------- RMSNorm (one block per row) ----------------
__global__ void rms_kernel(const float* __restrict__ in, const float* __restrict__ w,
                           float* __restrict__ out, int N) {
    int row = blockIdx.x;
    const float* x = in + (size_t)row * N;
    float ss = 0.f;
    for (int i = threadIdx.x; i < N; i += 128) { float v = x[i]; ss = fmaf(v, v, ss); }
    ss += __shfl_xor_sync(0xffffffffu, ss, 16);
    ss += __shfl_xor_sync(0xffffffffu, ss, 8);
    ss += __shfl_xor_sync(0xffffffffu, ss, 4);
    ss += __shfl_xor_sync(0xffffffffu, ss, 2);
    ss += __shfl_xor_sync(0xffffffffu, ss, 1);
    __shared__ float red[4];
    if ((threadIdx.x & 31) == 0) red[threadIdx.x >> 5] = ss;
    __syncthreads();
    float tot = red[0] + red[1] + red[2] + red[3];
    float r = rsqrtf(tot / (float)N + 1e-6f);
    for (int i = threadIdx.x; i < N; i += 128)
        out[(size_t)row*N + i] = x[i] * r * w[i];
}

// ---------------- SGEMM: C[M,N] = A[M,K] @ B[N,K]^T + bias[N] ----------------
// 128x128 tile, 8x8 micro, BK=16, 256 threads.
__global__ __launch_bounds__(256) void sgemm_nt_bias(
    const float* __restrict__ A, const float* __restrict__ B,
    const float* __restrict__ bias, float* __restrict__ C,
    int M, int N, int K)
{
    __shared__ float sA[16][132];
    __shared__ float sB[16][132];
    const int mt = blockIdx.x * 128;
    const int nt = blockIdx.y * 128;
    const int tid = threadIdx.x;
    const int ty = tid >> 4, tx = tid & 15;

    float acc[8][8];
    #pragma unroll
    for (int i = 0; i < 8; i++)
        #pragma unroll
        for (int j = 0; j < 8; j++) acc[i][j] = 0.f;

    for (int k0 = 0; k0 < K; k0 += 16) {
        __syncthreads();
        #pragma unroll
        for (int s = 0; s < 2; s++) {
            int f = tid + s * 256;          // 0..511
            int r  = f >> 2;                // 0..127
            int kk = (f & 3) << 2;          // 0,4,8,12
            float4 av = *(const float4*)&A[(size_t)(mt + r)*K + k0 + kk];
            sA[kk+0][r] = av.x; sA[kk+1][r] = av.y; sA[kk+2][r] = av.z; sA[kk+3][r] = av.w;
            float4 bv = *(const float4*)&B[(size_t)(nt + r)*K + k0 + kk];
            sB[kk+0][r] = bv.x; sB[kk+1][r] = bv.y; sB[kk+2][r] = bv.z; sB[kk+3][r] = bv.w;
        }
        __syncthreads();
        #pragma unroll
        for (int kk = 0; kk < 16; kk++) {
            float a[8], b[8];
            *(float4*)&a[0] = *(const float4*)&sA[kk][ty*8];
            *(float4*)&a[4] = *(const float4*)&sA[kk][ty*8 + 4];
            *(float4*)&b[0] = *(const float4*)&sB[kk][tx*8];
            *(float4*)&b[4] = *(const float4*)&sB[kk][tx*8 + 4];
            #pragma unroll
            for (int i = 0; i < 8; i++)
                #pragma unroll
                for (int j = 0; j < 8; j++) acc[i][j] = fmaf(a[i], b[j], acc[i][j]);
        }
    }
    #pragma unroll
    for (int i = 0; i < 8; i++) {
        size_t row = (size_t)(mt + ty*8 + i);
        #pragma unroll
        for (int j = 0; j < 8; j++) acc[i][j] += bias[nt + tx*8 + j];
        *(float4*)&C[row*N + nt + tx*8]     = make_float4(acc[i][0], acc[i][1], acc[i][2], acc[i][3]);
        *(float4*)&C[row*N + nt + tx*8 + 4] = make_float4(acc[i][4], acc[i][5], acc[i][6], acc[i][7]);
    }
}

// ---------------- Flash attention in latent space ----------------
// Q = g_qkv[b,:,h,:], K = V = g_kvn[b]. One block per (qtile=64, h, b).
// smem: QT[128][64] | KT[128][64] | V[64][128] | P[64][64]  = 112 KB
__global__ __launch_bounds__(256) void attn_kernel(
    const float* __restrict__ qkv, const float* __restrict__ kvn,
    float* __restrict__ vlat)
{
    extern __shared__ float sm[];
    float* sQ = sm;            // [128][64] (k-major)
    float* sK = sm + 8192;     // [128][64] (k-major)
    float* sV = sm + 16384;    // [64][128] (row-major)
    float* sP = sm + 24576;    // [64][64]

    const int qt = blockIdx.x, h = blockIdx.y, b = blockIdx.z;
    const int tid = threadIdx.x;
    const int ty = tid >> 4, tx = tid & 15;
    const int q0 = qt * 64;
    const int r0 = ty * 4, c0 = tx * 4, oc0 = tx * 8;
    const float scale = 0.2236067977499790f;   // 1/sqrt(20)

    // load Q tile transposed
    for (int idx = tid; idx < 2048; idx += 256) {
        int q = idx & 63, kc = idx >> 6;
        float4 v = *(const float4*)&qkv[((size_t)((b*SQ + q0 + q)*NH + h) << 7) + (kc << 2)];
        sQ[(kc*4+0)*64 + q] = v.x; sQ[(kc*4+1)*64 + q] = v.y;
        sQ[(kc*4+2)*64 + q] = v.z; sQ[(kc*4+3)*64 + q] = v.w;
    }

    float o[4][8];
    float m[4], l[4];
    #pragma unroll
    for (int i = 0; i < 4; i++) {
        m[i] = -1e30f; l[i] = 0.f;
        #pragma unroll
        for (int j = 0; j < 8; j++) o[i][j] = 0.f;
    }

    for (int kt = 0; kt <= qt; ++kt) {
        const int k0 = kt * 64;
        __syncthreads();   // prior PV done before overwriting K/V (also fences Q load at kt=0... Q is fenced by next sync)
        for (int idx = tid; idx < 2048; idx += 256) {
            int ky = idx & 63, kc = idx >> 6;
            float4 v = *(const float4*)&kvn[((size_t)(b*SQ + k0 + ky) << 7) + (kc << 2)];
            sK[(kc*4+0)*64 + ky] = v.x; sK[(kc*4+1)*64 + ky] = v.y;
            sK[(kc*4+2)*64 + ky] = v.z; sK[(kc*4+3)*64 + ky] = v.w;
            *(float4*)&sV[ky*128 + kc*4] = v;
        }
        __syncthreads();

        // S = Q @ K^T (4x4 micro-tile per thread)
        float s[4][4];
        #pragma unroll
        for (int i = 0; i < 4; i++)
            #pragma unroll
            for (int j = 0; j < 4; j++) s[i][j] = 0.f;
        #pragma unroll 8
        for (int k = 0; k < 128; k++) {
            float qa[4], ka[4];
            *(float4*)qa = *(const float4*)&sQ[k*64 + r0];
            *(float4*)ka = *(const float4*)&sK[k*64 + c0];
            #pragma unroll
            for (int i = 0; i < 4; i++)
                #pragma unroll
                for (int j = 0; j < 4; j++) s[i][j] = fmaf(qa[i], ka[j], s[i][j]);
        }

        const bool diag = (kt == qt);
        #pragma unroll
        for (int i = 0; i < 4; i++) {
            const int gq = q0 + r0 + i;
            float mm = -1e30f;
            #pragma unroll
            for (int j = 0; j < 4; j++) {
                float sv = s[i][j] * scale;
                if (diag && (k0 + c0 + j > gq)) sv = -1e30f;
                s[i][j] = sv;
                mm = fmaxf(mm, sv);
            }
            mm = fmaxf(mm, __shfl_xor_sync(0xffffffffu, mm, 1));
            mm = fmaxf(mm, __shfl_xor_sync(0xffffffffu, mm, 2));
            mm = fmaxf(mm, __shfl_xor_sync(0xffffffffu, mm, 4));
            mm = fmaxf(mm, __shfl_xor_sync(0xffffffffu, mm, 8));
            float mn = fmaxf(m[i], mm);
            float alpha = __expf(m[i] - mn);
            float ls = 0.f;
            #pragma unroll
            for (int j = 0; j < 4; j++) { float p = __expf(s[i][j] - mn); s[i][j] = p; ls += p; }
            ls += __shfl_xor_sync(0xffffffffu, ls, 1);
            ls += __shfl_xor_sync(0xffffffffu, ls, 2);
            ls += __shfl_xor_sync(0xffffffffu, ls, 4);
            ls += __shfl_xor_sync(0xffffffffu, ls, 8);
            l[i] = l[i]*alpha + ls;
            m[i] = mn;
            #pragma unroll
            for (int j = 0; j < 8; j++) o[i][j] *= alpha;
            *(float4*)&sP[(r0+i)*64 + c0] = make_float4(s[i][0], s[i][1], s[i][2], s[i][3]);
        }
        __syncthreads();

        // O += P @ V (4 rows x 8 cols per thread; P reads are broadcast)
        #pragma unroll 4
        for (int kk = 0; kk < 64; kk++) {
            float pv[4];
            pv[0] = sP[(r0+0)*64 + kk];
            pv[1] = sP[(r0+1)*64 + kk];
            pv[2] = sP[(r0+2)*64 + kk];
            pv[3] = sP[(r0+3)*64 + kk];
            float vv[8];
            *(float4*)&vv[0] = *(const float4*)&sV[kk*128 + oc0];
            *(float4*)&vv[4] = *(const float4*)&sV[kk*128 + oc0 + 4];
            #pragma unroll
            for (int i = 0; i < 4; i++)
                #pragma unroll
                for (int j = 0; j < 8; j++) o[i][j] = fmaf(pv[i], vv[j], o[i][j]);
        }
    }

    #pragma unroll
    for (int i = 0; i < 4; i++) {
        float inv = 1.f / l[i];
        int gq = q0 + r0 + i;
        size_t base = ((size_t)((b*SQ + gq)*NH + h) << 7) + oc0;
        *(float4*)&vlat[base]     = make_float4(o[i][0]*inv, o[i][1]*inv, o[i][2]*inv, o[i][3]*inv);
        *(float4*)&vlat[base + 4] = make_float4(o[i][4]*inv, o[i][5]*inv, o[i][6]*inv, o[i][7]*inv);
    }
}

// ---------------- launch ----------------
extern "C" void kernel_launch(void* const* d_in, const int* in_sizes, int n_in,
                              void* d_out, int out_size)
{
    const float* h_ptr     = (const float*)d_in[0];
    // d_in[1] = mask (causal tril) — handled analytically in attn_kernel
    const float* wq_a_w    = (const float*)d_in[2];
    const float* wq_a_b    = (const float*)d_in[3];
    const float* q_norm_w  = (const float*)d_in[4];
    const float* wq_b_w    = (const float*)d_in[5];
    const float* wq_b_b    = (const float*)d_in[6];
    const float* wkv_a_w   = (const float*)d_in[7];
    const float* wkv_a_b   = (const float*)d_in[8];
    const float* kv_norm_w = (const float*)d_in[9];
    const float* wkv_b_w   = (const float*)d_in[10];
    const float* wo_w      = (const float*)d_in[11];
    const float* wo_b      = (const float*)d_in[12];
    float* out = (float*)d_out;

    float *qraw, *kraw, *qlat, *kvn, *qkv, *vlat, *wc, *biasc, *wo2;
    cudaGetSymbolAddress((void**)&qraw,  g_qraw);
    cudaGetSymbolAddress((void**)&kraw,  g_kraw);
    cudaGetSymbolAddress((void**)&qlat,  g_qlat);
    cudaGetSymbolAddress((void**)&kvn,   g_kvn);
    cudaGetSymbolAddress((void**)&qkv,   g_qkv);
    cudaGetSymbolAddress((void**)&vlat,  g_vlat);
    cudaGetSymbolAddress((void**)&wc,    g_wc);
    cudaGetSymbolAddress((void**)&biasc, g_biasc);
    cudaGetSymbolAddress((void**)&wo2,   g_wo2);

    cudaFuncSetAttribute(attn_kernel, cudaFuncAttributeMaxDynamicSharedMemorySize, 114688);

    // weight absorption (cheap, recomputed every call for determinism)
    prep_wc_kernel<<<NH*DLKV, DLQ>>>(wq_b_w, wq_b_b, wkv_b_w, wc, biasc);
    prep_wo2_kernel<<<dim3(DIM, NH), DLKV>>>(wo_w, wkv_b_w, wo2);

    // latent projections + RMSNorm
    sgemm_nt_bias<<<dim3(NTOK/128, DLQ/128),  256>>>(h_ptr, wq_a_w,  wq_a_b,  qraw, NTOK, DLQ,  DIM);
    sgemm_nt_bias<<<dim3(NTOK/128, DLKV/128), 256>>>(h_ptr, wkv_a_w, wkv_a_b, kraw, NTOK, DLKV, DIM);
    rms_kernel<<<NTOK, 128>>>(qraw, q_norm_w,  qlat, DLQ);
    rms_kernel<<<NTOK, 128>>>(kraw, kv_norm_w, kvn,  DLKV);

    // absorbed q -> latent-kv space: [8192,256] x [2048,256]^T
    sgemm_nt_bias<<<dim3(NTOK/128, (NH*DLKV)/128), 256>>>(qlat, wc, biasc, qkv, NTOK, NH*DLKV, DLQ);

    // flash attention in latent space
    attn_kernel<<<dim3(SQ/64, NH, BB), 256, 114688>>>(qkv, kvn, vlat);

    // absorbed v -> output: [8192,2048] x [1024,2048]^T + wo_b
    sgemm_nt_bias<<<dim3(NTOK/128, DIM/128), 256>>>(vlat, wo2, wo_b, out, NTOK, DIM, NH*DLKV);
}

// round 3
// speedup vs baseline: 2.9385x; 2.9260x over previous
#include <cuda_runtime.h>
#include <cstdint>

#define SQ   2048
#define BB   4
#define DIM  1024
#define NH   16
#define NDQK 20
#define NDV  64
#define DLQ  256
#define DLKV 128
#define NTOK (BB*SQ)

__device__ float g_qraw[NTOK*DLQ];
__device__ float g_kraw[NTOK*DLKV];
__device__ float g_qlat[NTOK*DLQ];
__device__ float g_kvn [NTOK*DLKV];
__device__ float g_qkv [(size_t)NTOK*NH*DLKV];
__device__ float g_vlat[(size_t)NTOK*NH*DLKV];
__device__ float g_wc  [NH*DLKV*DLQ];
__device__ float g_biasc[NH*DLKV];
__device__ float g_wo2 [DIM*NH*DLKV];

__device__ __forceinline__ uint32_t f2tf(float f){
    uint32_t u; asm("cvt.rna.tf32.f32 %0, %1;" : "=r"(u) : "f"(f)); return u;
}
__device__ __forceinline__ void mma8(float&c0,float&c1,float&c2,float&c3,
    uint32_t a0,uint32_t a1,uint32_t a2,uint32_t a3,uint32_t b0,uint32_t b1){
    asm volatile("mma.sync.aligned.m16n8k8.row.col.f32.tf32.tf32.f32 "
        "{%0,%1,%2,%3}, {%4,%5,%6,%7}, {%8,%9}, {%0,%1,%2,%3};"
        : "+f"(c0),"+f"(c1),"+f"(c2),"+f"(c3)
        : "r"(a0),"r"(a1),"r"(a2),"r"(a3),"r"(b0),"r"(b1));
}

// ---------- weight absorption (tiny) ----------
__global__ void prep_wc_kernel(const float* __restrict__ wq_b_w,
                               const float* __restrict__ wq_b_b,
                               const float* __restrict__ wkv_b_w,
                               float* __restrict__ wc, float* __restrict__ biasc) {
    int hc = blockIdx.x, h = hc >> 7, c = hc & 127, l = threadIdx.x;
    float acc = 0.f, accb = 0.f;
    #pragma unroll
    for (int q = 0; q < NDQK; q++) {
        float kb = wkv_b_w[(size_t)(h*(NDQK+NDV) + q)*DLKV + c];
        acc  = fmaf(kb, wq_b_w[(size_t)(h*NDQK + q)*DLQ + l], acc);
        accb = fmaf(kb, wq_b_b[h*NDQK + q], accb);
    }
    wc[(size_t)hc*DLQ + l] = acc;
    if (l == 0) biasc[hc] = accb;
}
__global__ void prep_wo2_kernel(const float* __restrict__ wo_w,
                                const float* __restrict__ wkv_b_w,
                                float* __restrict__ wo2) {
    int d = blockIdx.x, h = blockIdx.y, c = threadIdx.x;
    float acc = 0.f;
    #pragma unroll 8
    for (int v = 0; v < NDV; v++)
        acc = fmaf(wo_w[(size_t)d*(NH*NDV) + h*NDV + v],
                   wkv_b_w[(size_t)(h*(NDQK+NDV) + NDQK + v)*DLKV + c], acc);
    wo2[(size_t)d*(NH*DLKV) + h*DLKV + c] = acc;
}

// ---------- RMSNorm ----------
__global__ void rms_kernel(const float* __restrict__ in, const float* __restrict__ w,
                           float* __restrict__ out, int N) {
    int row = blockIdx.x;
    const float* x = in + (size_t)row * N;
    float ss = 0.f;
    for (int i = threadIdx.x; i < N; i += 128) { float v = x[i]; ss = fmaf(v, v, ss); }
    #pragma unroll
    for (int d = 16; d; d >>= 1) ss += __shfl_xor_sync(0xffffffffu, ss, d);
    __shared__ float red[4];
    if ((threadIdx.x & 31) == 0) red[threadIdx.x >> 5] = ss;
    __syncthreads();
    float r = rsqrtf((red[0]+red[1]+red[2]+red[3]) / (float)N + 1e-6f);
    for (int i = threadIdx.x; i < N; i += 128)
        out[(size_t)row*N + i] = x[i] * r * w[i];
}

// ---------- tf32 tensor GEMM: C[M,N] = A[M,K] @ B[N,K]^T + bias ----------
// 128x128 tile, BK=16, 256 thr (8 warps: 4 along M x 2 along N, warp tile 32x64)
__global__ __launch_bounds__(256) void tgemm_nt_bias(
    const float* __restrict__ A, const float* __restrict__ B,
    const float* __restrict__ bias, float* __restrict__ C,
    int M, int N, int K)
{
    __shared__ uint32_t sA[128*20];
    __shared__ uint32_t sB[128*20];
    const int mt = blockIdx.x*128, nt = blockIdx.y*128;
    const int tid = threadIdx.x, w = tid>>5, lane = tid&31;
    const int g = lane>>2, t = lane&3;
    const int wm = (w&3)*32, wn = (w>>2)*64;

    float acc[2][8][4];
    #pragma unroll
    for (int i=0;i<2;i++)
        #pragma unroll
        for (int j=0;j<8;j++)
            #pragma unroll
            for (int r=0;r<4;r++) acc[i][j][r]=0.f;

    for (int k0=0; k0<K; k0+=16){
        __syncthreads();
        #pragma unroll
        for (int i=0;i<2;i++){
            int f = tid + i*256;
            int r = f>>2, c4 = (f&3)<<2;
            float4 av = *(const float4*)&A[(size_t)(mt+r)*K + k0 + c4];
            uint32_t* da = &sA[r*20 + c4];
            da[0]=f2tf(av.x); da[1]=f2tf(av.y); da[2]=f2tf(av.z); da[3]=f2tf(av.w);
            float4 bv = *(const float4*)&B[(size_t)(nt+r)*K + k0 + c4];
            uint32_t* db = &sB[r*20 + c4];
            db[0]=f2tf(bv.x); db[1]=f2tf(bv.y); db[2]=f2tf(bv.z); db[3]=f2tf(bv.w);
        }
        __syncthreads();
        #pragma unroll
        for (int kk=0; kk<16; kk+=8){
            uint32_t af[2][4], bf[8][2];
            #pragma unroll
            for (int i=0;i<2;i++){
                int mb = wm + i*16;
                af[i][0]=sA[(mb+g  )*20+kk+t];   af[i][1]=sA[(mb+g+8)*20+kk+t];
                af[i][2]=sA[(mb+g  )*20+kk+t+4]; af[i][3]=sA[(mb+g+8)*20+kk+t+4];
            }
            #pragma unroll
            for (int j=0;j<8;j++){
                int nb = wn + j*8;
                bf[j][0]=sB[(nb+g)*20+kk+t]; bf[j][1]=sB[(nb+g)*20+kk+t+4];
            }
            #pragma unroll
            for (int i=0;i<2;i++)
                #pragma unroll
                for (int j=0;j<8;j++)
                    mma8(acc[i][j][0],acc[i][j][1],acc[i][j][2],acc[i][j][3],
                         af[i][0],af[i][1],af[i][2],af[i][3],bf[j][0],bf[j][1]);
        }
    }
    #pragma unroll
    for (int i=0;i<2;i++){
        int row0 = mt + wm + i*16 + g, row1 = row0 + 8;
        #pragma unroll
        for (int j=0;j<8;j++){
            int col = nt + wn + j*8 + 2*t;
            float b0v = bias[col], b1v = bias[col+1];
            *(float2*)&C[(size_t)row0*N + col] = make_float2(acc[i][j][0]+b0v, acc[i][j][1]+b1v);
            *(float2*)&C[(size_t)row1*N + col] = make_float2(acc[i][j][2]+b0v, acc[i][j][3]+b1v);
        }
    }
}

// ---------- tensor-core flash attention in 128-dim latent space ----------
// block = (qtile 64, h, b), 128 threads (4 warps, 16 rows each). K tile == V tile.
__global__ __launch_bounds__(128) void attn_tc(
    const float* __restrict__ qkv, const float* __restrict__ kvn,
    float* __restrict__ vlat)
{
    extern __shared__ uint32_t sm[];
    uint32_t* sQ  = sm;                 // [64][132] tf32
    uint32_t* sKV = sm + 64*132;        // [64][132] tf32
    uint32_t* sP  = sm + 2*64*132;      // [64][68]  tf32

    const int qt = blockIdx.x, h = blockIdx.y, b = blockIdx.z;
    const int tid = threadIdx.x, w = tid>>5, lane = tid&31;
    const int g = lane>>2, t = lane&3;
    const int q0 = qt*64;
    const int mrow = w*16 + g;          // local row (and +8)
    const float scale = 0.22360679774997896f;  // 1/sqrt(20)

    #pragma unroll
    for (int i=0;i<16;i++){
        int f = tid + i*128;
        int r = f>>5, c4 = (f&31)<<2;
        float4 v = *(const float4*)&qkv[((size_t)((b*SQ+q0+r)*NH + h))*128 + c4];
        uint32_t* d = &sQ[r*132 + c4];
        d[0]=f2tf(v.x); d[1]=f2tf(v.y); d[2]=f2tf(v.z); d[3]=f2tf(v.w);
    }

    float o[16][4];
    #pragma unroll
    for (int j=0;j<16;j++){ o[j][0]=0.f;o[j][1]=0.f;o[j][2]=0.f;o[j][3]=0.f; }
    float m0=-1e30f, m1=-1e30f, l0=0.f, l1=0.f;

    for (int kt=0; kt<=qt; kt++){
        const int k0 = kt*64;
        __syncthreads();
        #pragma unroll
        for (int i=0;i<16;i++){
            int f = tid + i*128;
            int r = f>>5, c4 = (f&31)<<2;
            float4 v = *(const float4*)&kvn[((size_t)(b*SQ+k0+r))*128 + c4];
            uint32_t* d = &sKV[r*132 + c4];
            d[0]=f2tf(v.x); d[1]=f2tf(v.y); d[2]=f2tf(v.z); d[3]=f2tf(v.w);
        }
        __syncthreads();

        // S = Q @ K^T  (warp: 16 rows x 64 cols, k=128)
        float s[8][4];
        #pragma unroll
        for (int j=0;j<8;j++){ s[j][0]=0.f;s[j][1]=0.f;s[j][2]=0.f;s[j][3]=0.f; }
        #pragma unroll
        for (int kk=0; kk<128; kk+=8){
            uint32_t a0=sQ[(mrow  )*132+kk+t],   a1=sQ[(mrow+8)*132+kk+t];
            uint32_t a2=sQ[(mrow  )*132+kk+t+4], a3=sQ[(mrow+8)*132+kk+t+4];
            #pragma unroll
            for (int j=0;j<8;j++){
                uint32_t b0=sKV[(j*8+g)*132+kk+t], b1=sKV[(j*8+g)*132+kk+t+4];
                mma8(s[j][0],s[j][1],s[j][2],s[j][3],a0,a1,a2,a3,b0,b1);
            }
        }

        // scale + causal mask + online softmax
        const bool diag = (kt==qt);
        const int grow0 = q0 + mrow, grow1 = grow0 + 8;
        float mx0=-1e30f, mx1=-1e30f;
        #pragma unroll
        for (int j=0;j<8;j++){
            int c = k0 + j*8 + 2*t;
            #pragma unroll
            for (int e=0;e<2;e++){
                float v0 = s[j][e]*scale, v1 = s[j][2+e]*scale;
                if (diag && (c+e) > grow0) v0 = -1e30f;
                if (diag && (c+e) > grow1) v1 = -1e30f;
                s[j][e] = v0; s[j][2+e] = v1;
                mx0 = fmaxf(mx0, v0); mx1 = fmaxf(mx1, v1);
            }
        }
        mx0 = fmaxf(mx0, __shfl_xor_sync(0xffffffffu, mx0, 1));
        mx0 = fmaxf(mx0, __shfl_xor_sync(0xffffffffu, mx0, 2));
        mx1 = fmaxf(mx1, __shfl_xor_sync(0xffffffffu, mx1, 1));
        mx1 = fmaxf(mx1, __shfl_xor_sync(0xffffffffu, mx1, 2));
        float nm0 = fmaxf(m0, mx0), nm1 = fmaxf(m1, mx1);
        float al0 = __expf(m0 - nm0), al1 = __expf(m1 - nm1);
        m0 = nm0; m1 = nm1;
        float ls0 = 0.f, ls1 = 0.f;
        #pragma unroll
        for (int j=0;j<8;j++){
            float p00 = __expf(s[j][0]-nm0), p01 = __expf(s[j][1]-nm0);
            float p10 = __expf(s[j][2]-nm1), p11 = __expf(s[j][3]-nm1);
            ls0 += p00 + p01; ls1 += p10 + p11;
            int c = j*8 + 2*t;
            sP[(mrow  )*68 + c] = f2tf(p00); sP[(mrow  )*68 + c+1] = f2tf(p01);
            sP[(mrow+8)*68 + c] = f2tf(p10); sP[(mrow+8)*68 + c+1] = f2tf(p11);
        }
        ls0 += __shfl_xor_sync(0xffffffffu, ls0, 1);
        ls0 += __shfl_xor_sync(0xffffffffu, ls0, 2);
        ls1 += __shfl_xor_sync(0xffffffffu, ls1, 1);
        ls1 += __shfl_xor_sync(0xffffffffu, ls1, 2);
        l0 = l0*al0 + ls0; l1 = l1*al1 + ls1;
        #pragma unroll
        for (int j=0;j<16;j++){ o[j][0]*=al0; o[j][1]*=al0; o[j][2]*=al1; o[j][3]*=al1; }
        __syncwarp();

        // O += P @ V  (warp: 16 rows x 128 cols, k=64; V rows = sKV rows)
        #pragma unroll
        for (int kb=0; kb<64; kb+=8){
            uint32_t a0=sP[(mrow  )*68+kb+t],   a1=sP[(mrow+8)*68+kb+t];
            uint32_t a2=sP[(mrow  )*68+kb+t+4], a3=sP[(mrow+8)*68+kb+t+4];
            #pragma unroll
            for (int j=0;j<16;j++){
                uint32_t b0=sKV[(kb+t  )*132 + j*8+g], b1=sKV[(kb+t+4)*132 + j*8+g];
                mma8(o[j][0],o[j][1],o[j][2],o[j][3],a0,a1,a2,a3,b0,b1);
            }
        }
    }

    float inv0 = 1.f/l0, inv1 = 1.f/l1;
    int grow0 = q0 + mrow;
    #pragma unroll
    for (int j=0;j<16;j++){
        int col = j*8 + 2*t;
        size_t base0 = ((size_t)((b*SQ+grow0  )*NH + h))*128 + col;
        size_t base1 = ((size_t)((b*SQ+grow0+8)*NH + h))*128 + col;
        *(float2*)&vlat[base0] = make_float2(o[j][0]*inv0, o[j][1]*inv0);
        *(float2*)&vlat[base1] = make_float2(o[j][2]*inv1, o[j][3]*inv1);
    }
}

// ---------- launch ----------
extern "C" void kernel_launch(void* const* d_in, const int* in_sizes, int n_in,
                              void* d_out, int out_size)
{
    const float* h_ptr     = (const float*)d_in[0];
    const float* wq_a_w    = (const float*)d_in[2];
    const float* wq_a_b    = (const float*)d_in[3];
    const float* q_norm_w  = (const float*)d_in[4];
    const float* wq_b_w    = (const float*)d_in[5];
    const float* wq_b_b    = (const float*)d_in[6];
    const float* wkv_a_w   = (const float*)d_in[7];
    const float* wkv_a_b   = (const float*)d_in[8];
    const float* kv_norm_w = (const float*)d_in[9];
    const float* wkv_b_w   = (const float*)d_in[10];
    const float* wo_w      = (const float*)d_in[11];
    const float* wo_b      = (const float*)d_in[12];
    float* out = (float*)d_out;

    float *qraw, *kraw, *qlat, *kvn, *qkv, *vlat, *wc, *biasc, *wo2;
    cudaGetSymbolAddress((void**)&qraw,  g_qraw);
    cudaGetSymbolAddress((void**)&kraw,  g_kraw);
    cudaGetSymbolAddress((void**)&qlat,  g_qlat);
    cudaGetSymbolAddress((void**)&kvn,   g_kvn);
    cudaGetSymbolAddress((void**)&qkv,   g_qkv);
    cudaGetSymbolAddress((void**)&vlat,  g_vlat);
    cudaGetSymbolAddress((void**)&wc,    g_wc);
    cudaGetSymbolAddress((void**)&biasc, g_biasc);
    cudaGetSymbolAddress((void**)&wo2,   g_wo2);

    static int attn_smem = 2*64*132*4 + 64*68*4;   // 84992 B
    cudaFuncSetAttribute(attn_tc, cudaFuncAttributeMaxDynamicSharedMemorySize, attn_smem);

    prep_wc_kernel<<<NH*DLKV, DLQ>>>(wq_b_w, wq_b_b, wkv_b_w, wc, biasc);
    prep_wo2_kernel<<<dim3(DIM, NH), DLKV>>>(wo_w, wkv_b_w, wo2);

    tgemm_nt_bias<<<dim3(NTOK/128, DLQ/128),  256>>>(h_ptr, wq_a_w,  wq_a_b,  qraw, NTOK, DLQ,  DIM);
    tgemm_nt_bias<<<dim3(NTOK/128, DLKV/128), 256>>>(h_ptr, wkv_a_w, wkv_a_b, kraw, NTOK, DLKV, DIM);
    rms_kernel<<<NTOK, 128>>>(qraw, q_norm_w,  qlat, DLQ);
    rms_kernel<<<NTOK, 128>>>(kraw, kv_norm_w, kvn,  DLKV);

    tgemm_nt_bias<<<dim3(NTOK/128, (NH*DLKV)/128), 256>>>(qlat, wc, biasc, qkv, NTOK, NH*DLKV, DLQ);

    attn_tc<<<dim3(SQ/64, NH, BB), 128, attn_smem>>>(qkv, kvn, vlat);

    tgemm_nt_bias<<<dim3(NTOK/128, DIM/128), 256>>>(vlat, wo2, wo_b, out, NTOK, DIM, NH*DLKV);
}

// round 5
// speedup vs baseline: 3.2724x; 1.1136x over previous
#include <cuda_runtime.h>
#include <cstdint>

#define SQ   2048
#define BB   4
#define DIM  1024
#define NH   16
#define NDQK 20
#define NDV  64
#define DLQ  256
#define DLKV 128
#define NTOK (BB*SQ)

__device__ float g_projcat[(size_t)NTOK*384];
__device__ float g_qlat[NTOK*DLQ];
__device__ float g_kvn [NTOK*DLKV];
__device__ float g_qkv [(size_t)NTOK*NH*DLKV];
__device__ float g_vlat[(size_t)NTOK*NH*DLKV];
__device__ float g_wc  [NH*DLKV*DLQ];
__device__ float g_biasc[NH*DLKV];
__device__ float g_wo2 [DIM*NH*DLKV];
__device__ float g_wcat[384*DIM];
__device__ float g_bcat[384];

// ======================= helpers =======================
__device__ __forceinline__ uint32_t f2tf(float f){
    uint32_t u; asm("cvt.rna.tf32.f32 %0, %1;" : "=r"(u) : "f"(f)); return u;
}
__device__ __forceinline__ void mma8(float&c0,float&c1,float&c2,float&c3,
    uint32_t a0,uint32_t a1,uint32_t a2,uint32_t a3,uint32_t b0,uint32_t b1){
    asm volatile("mma.sync.aligned.m16n8k8.row.col.f32.tf32.tf32.f32 "
        "{%0,%1,%2,%3}, {%4,%5,%6,%7}, {%8,%9}, {%0,%1,%2,%3};"
        : "+f"(c0),"+f"(c1),"+f"(c2),"+f"(c3)
        : "r"(a0),"r"(a1),"r"(a2),"r"(a3),"r"(b0),"r"(b1));
}
__device__ __forceinline__ uint32_t smem_u32(const void* p){
    uint32_t a;
    asm("{ .reg .u64 t; cvta.to.shared.u64 t, %1; cvt.u32.u64 %0, t; }" : "=r"(a) : "l"(p));
    return a;
}
__device__ __forceinline__ void cp16(uint32_t dst, const void* src){
    asm volatile("cp.async.cg.shared.global [%0], [%1], 16;" :: "r"(dst), "l"(src));
}
__device__ __forceinline__ void cp_commit(){ asm volatile("cp.async.commit_group;" ::: "memory"); }
template<int NW> __device__ __forceinline__ void cp_wait(){
    asm volatile("cp.async.wait_group %0;" :: "n"(NW) : "memory");
}

// ---------- weight prep ----------
__global__ void prep_wcat(const float* __restrict__ wq_a_w, const float* __restrict__ wq_a_b,
                          const float* __restrict__ wkv_a_w, const float* __restrict__ wkv_a_b,
                          float* __restrict__ wcat, float* __restrict__ bcat){
    int n = blockIdx.x;
    const float* src = (n < 256) ? (wq_a_w + (size_t)n*DIM) : (wkv_a_w + (size_t)(n-256)*DIM);
    for (int k = threadIdx.x; k < DIM; k += 256) wcat[(size_t)n*DIM + k] = src[k];
    if (threadIdx.x == 0) bcat[n] = (n < 256) ? wq_a_b[n] : wkv_a_b[n-256];
}
__global__ void prep_wc_kernel(const float* __restrict__ wq_b_w,
                               const float* __restrict__ wq_b_b,
                               const float* __restrict__ wkv_b_w,
                               float* __restrict__ wc, float* __restrict__ biasc) {
    int hc = blockIdx.x, h = hc >> 7, c = hc & 127, l = threadIdx.x;
    float acc = 0.f, accb = 0.f;
    #pragma unroll
    for (int q = 0; q < NDQK; q++) {
        float kb = wkv_b_w[(size_t)(h*(NDQK+NDV) + q)*DLKV + c];
        acc  = fmaf(kb, wq_b_w[(size_t)(h*NDQK + q)*DLQ + l], acc);
        accb = fmaf(kb, wq_b_b[h*NDQK + q], accb);
    }
    wc[(size_t)hc*DLQ + l] = acc;
    if (l == 0) biasc[hc] = accb;
}
__global__ void prep_wo2_kernel(const float* __restrict__ wo_w,
                                const float* __restrict__ wkv_b_w,
                                float* __restrict__ wo2) {
    int d = blockIdx.x, h = blockIdx.y, c = threadIdx.x;
    float acc = 0.f;
    #pragma unroll 8
    for (int v = 0; v < NDV; v++)
        acc = fmaf(wo_w[(size_t)d*(NH*NDV) + h*NDV + v],
                   wkv_b_w[(size_t)(h*(NDQK+NDV) + NDQK + v)*DLKV + c], acc);
    wo2[(size_t)d*(NH*DLKV) + h*DLKV + c] = acc;
}

// ---------- RMSNorm (strided input) ----------
__global__ void rms_kernel(const float* __restrict__ in, int ld, int off,
                           const float* __restrict__ w, float* __restrict__ out, int N) {
    int row = blockIdx.x;
    const float* x = in + (size_t)row*ld + off;
    float ss = 0.f;
    for (int i = threadIdx.x; i < N; i += 128) { float v = x[i]; ss = fmaf(v, v, ss); }
    #pragma unroll
    for (int d = 16; d; d >>= 1) ss += __shfl_xor_sync(0xffffffffu, ss, d);
    __shared__ float red[4];
    if ((threadIdx.x & 31) == 0) red[threadIdx.x >> 5] = ss;
    __syncthreads();
    float r = rsqrtf((red[0]+red[1]+red[2]+red[3]) / (float)N + 1e-6f);
    for (int i = threadIdx.x; i < N; i += 128)
        out[(size_t)row*N + i] = x[i] * r * w[i];
}

// ---------- tf32 mma GEMM, cp.async 2-stage, 128x128 tile, BK=32 ----------
// C[M,N] = A[M,K] @ B[N,K]^T + bias[N]
__global__ __launch_bounds__(256) void tgemm2(
    const float* __restrict__ A, const float* __restrict__ Bm,
    const float* __restrict__ bias, float* __restrict__ C,
    int M, int N, int K)
{
    extern __shared__ float smem[];
    float* sA = smem;                  // [2][128][36]
    float* sB = smem + 2*128*36;       // [2][128][36]

    const int mt = blockIdx.y*128, nt = blockIdx.x*128;
    const int tid = threadIdx.x, w = tid>>5, lane = tid&31;
    const int g = lane>>2, t = lane&3;
    const int wm = (w&3)*32, wn = (w>>2)*64;

    float acc[2][8][4];
    #pragma unroll
    for (int i=0;i<2;i++)
        #pragma unroll
        for (int j=0;j<8;j++){ acc[i][j][0]=0.f; acc[i][j][1]=0.f; acc[i][j][2]=0.f; acc[i][j][3]=0.f; }

    const int NC = K >> 5;
    // prefetch stage 0
    {
        #pragma unroll
        for (int s2=0;s2<4;s2++){
            int v = tid + s2*256, r = v>>3, c4 = (v&7)<<2;
            cp16(smem_u32(&sA[r*36 + c4]), &A [(size_t)(mt+r)*K + c4]);
            cp16(smem_u32(&sB[r*36 + c4]), &Bm[(size_t)(nt+r)*K + c4]);
        }
        cp_commit();
    }
    for (int i=0;i<NC;i++){
        const int st = i&1;
        __syncthreads();      // stage 1-st free (prev compute done)
        if (i+1 < NC){
            const int k0 = (i+1) << 5;
            float* dA = sA + (1-st)*128*36;
            float* dB = sB + (1-st)*128*36;
            #pragma unroll
            for (int s2=0;s2<4;s2++){
                int v = tid + s2*256, r = v>>3, c4 = (v&7)<<2;
                cp16(smem_u32(&dA[r*36 + c4]), &A [(size_t)(mt+r)*K + k0 + c4]);
                cp16(smem_u32(&dB[r*36 + c4]), &Bm[(size_t)(nt+r)*K + k0 + c4]);
            }
            cp_commit();
            cp_wait<1>();
        } else {
            cp_wait<0>();
        }
        __syncthreads();
        const float* cA = sA + st*128*36;
        const float* cB = sB + st*128*36;
        #pragma unroll
        for (int kk=0; kk<32; kk+=8){
            uint32_t af[2][4], bf[8][2];
            #pragma unroll
            for (int ii=0;ii<2;ii++){
                int mb = wm + ii*16;
                af[ii][0]=f2tf(cA[(mb+g  )*36+kk+t]);   af[ii][1]=f2tf(cA[(mb+g+8)*36+kk+t]);
                af[ii][2]=f2tf(cA[(mb+g  )*36+kk+t+4]); af[ii][3]=f2tf(cA[(mb+g+8)*36+kk+t+4]);
            }
            #pragma unroll
            for (int j=0;j<8;j++){
                int nb = wn + j*8;
                bf[j][0]=f2tf(cB[(nb+g)*36+kk+t]); bf[j][1]=f2tf(cB[(nb+g)*36+kk+t+4]);
            }
            #pragma unroll
            for (int ii=0;ii<2;ii++)
                #pragma unroll
                for (int j=0;j<8;j++)
                    mma8(acc[ii][j][0],acc[ii][j][1],acc[ii][j][2],acc[ii][j][3],
                         af[ii][0],af[ii][1],af[ii][2],af[ii][3],bf[j][0],bf[j][1]);
        }
    }
    #pragma unroll
    for (int ii=0;ii<2;ii++){
        int row0 = mt + wm + ii*16 + g, row1 = row0 + 8;
        #pragma unroll
        for (int j=0;j<8;j++){
            int col = nt + wn + j*8 + 2*t;
            float b0v = bias[col], b1v = bias[col+1];
            *(float2*)&C[(size_t)row0*N + col] = make_float2(acc[ii][j][0]+b0v, acc[ii][j][1]+b1v);
            *(float2*)&C[(size_t)row1*N + col] = make_float2(acc[ii][j][2]+b0v, acc[ii][j][3]+b1v);
        }
    }
}

// ---------- flash attention, cp.async double-buffered KV ----------
// block = (qtile 64, h, b), 128 threads / 4 warps.
__global__ __launch_bounds__(128) void attn_tc(
    const float* __restrict__ qkv, const float* __restrict__ kvn,
    float* __restrict__ vlat)
{
    extern __shared__ float smf[];
    float*    sKV = smf;                          // [2][64][132] raw fp32
    uint32_t* sP  = (uint32_t*)(smf + 2*64*132);  // [64][68] tf32 bits

    const int qt = (int)gridDim.x - 1 - (int)blockIdx.x;  // long blocks first
    const int h = blockIdx.y, b = blockIdx.z;
    const int tid = threadIdx.x, lane = tid & 31;
    const int g = lane >> 2, t = lane & 3;
    const int q0 = qt*64;
    const int mrow = (tid >> 5)*16 + g;
    const float scale = 0.22360679774997896f;

    // prefetch KV tile 0 -> buffer 0
    {
        #pragma unroll
        for (int s2=0;s2<16;s2++){
            int v = tid + s2*128, r = v>>5, c4 = (v&31)<<2;
            cp16(smem_u32(&sKV[r*132 + c4]), &kvn[((size_t)(b*SQ + r))*128 + c4]);
        }
        cp_commit();
    }
    // stage Q (tf32 bits) into buffer 1, then lift fragments to registers
    uint32_t* sQ = (uint32_t*)(sKV + 64*132);
    #pragma unroll
    for (int i = 0; i < 16; i++) {
        int f = tid + i*128, r = f >> 5, c4 = (f & 31) << 2;
        float4 v = *(const float4*)&qkv[((size_t)((b*SQ + q0 + r)*NH + h))*128 + c4];
        uint32_t* d = &sQ[r*132 + c4];
        d[0]=f2tf(v.x); d[1]=f2tf(v.y); d[2]=f2tf(v.z); d[3]=f2tf(v.w);
    }
    __syncthreads();
    uint32_t qf[16][4];
    #pragma unroll
    for (int kk = 0; kk < 16; kk++) {
        qf[kk][0] = sQ[(mrow  )*132 + kk*8 + t];
        qf[kk][1] = sQ[(mrow+8)*132 + kk*8 + t];
        qf[kk][2] = sQ[(mrow  )*132 + kk*8 + t + 4];
        qf[kk][3] = sQ[(mrow+8)*132 + kk*8 + t + 4];
    }

    float o[16][4];
    #pragma unroll
    for (int j = 0; j < 16; j++) { o[j][0]=0.f; o[j][1]=0.f; o[j][2]=0.f; o[j][3]=0.f; }
    float m0=-1e30f, m1=-1e30f, l0=0.f, l1=0.f;

    for (int kt = 0; kt <= qt; kt++) {
        const int st = kt & 1;
        __syncthreads();               // buffer 1-st free (prev compute / Q frag lift done)
        if (kt < qt) {
            const int k0n = (kt+1)*64;
            float* dst = sKV + (1-st)*64*132;
            #pragma unroll
            for (int s2=0;s2<16;s2++){
                int v = tid + s2*128, r = v>>5, c4 = (v&31)<<2;
                cp16(smem_u32(&dst[r*132 + c4]), &kvn[((size_t)(b*SQ + k0n + r))*128 + c4]);
            }
            cp_commit();
            cp_wait<1>();
        } else {
            cp_wait<0>();
        }
        __syncthreads();
        const float* cKV = sKV + st*64*132;
        const int k0 = kt*64;

        float s[8][4];
        #pragma unroll
        for (int j = 0; j < 8; j++) { s[j][0]=0.f; s[j][1]=0.f; s[j][2]=0.f; s[j][3]=0.f; }
        #pragma unroll
        for (int kk = 0; kk < 16; kk++) {
            #pragma unroll
            for (int j = 0; j < 8; j++) {
                uint32_t b0 = f2tf(cKV[(j*8+g)*132 + kk*8 + t]);
                uint32_t b1 = f2tf(cKV[(j*8+g)*132 + kk*8 + t + 4]);
                mma8(s[j][0],s[j][1],s[j][2],s[j][3], qf[kk][0],qf[kk][1],qf[kk][2],qf[kk][3], b0,b1);
            }
        }

        const bool diag = (kt == qt);
        const int grow0 = q0 + mrow, grow1 = grow0 + 8;
        float mx0=-1e30f, mx1=-1e30f;
        #pragma unroll
        for (int j = 0; j < 8; j++) {
            int c = k0 + j*8 + 2*t;
            #pragma unroll
            for (int e = 0; e < 2; e++) {
                float v0 = s[j][e]*scale, v1 = s[j][2+e]*scale;
                if (diag && (c+e) > grow0) v0 = -1e30f;
                if (diag && (c+e) > grow1) v1 = -1e30f;
                s[j][e] = v0; s[j][2+e] = v1;
                mx0 = fmaxf(mx0, v0); mx1 = fmaxf(mx1, v1);
            }
        }
        mx0 = fmaxf(mx0, __shfl_xor_sync(0xffffffffu, mx0, 1));
        mx0 = fmaxf(mx0, __shfl_xor_sync(0xffffffffu, mx0, 2));
        mx1 = fmaxf(mx1, __shfl_xor_sync(0xffffffffu, mx1, 1));
        mx1 = fmaxf(mx1, __shfl_xor_sync(0xffffffffu, mx1, 2));
        float nm0 = fmaxf(m0, mx0), nm1 = fmaxf(m1, mx1);
        float al0 = __expf(m0 - nm0), al1 = __expf(m1 - nm1);
        m0 = nm0; m1 = nm1;
        float ls0 = 0.f, ls1 = 0.f;
        #pragma unroll
        for (int j = 0; j < 8; j++) {
            float p00 = __expf(s[j][0]-nm0), p01 = __expf(s[j][1]-nm0);
            float p10 = __expf(s[j][2]-nm1), p11 = __expf(s[j][3]-nm1);
            ls0 += p00 + p01; ls1 += p10 + p11;
            int c = j*8 + 2*t;
            sP[(mrow  )*68 + c] = f2tf(p00); sP[(mrow  )*68 + c+1] = f2tf(p01);
            sP[(mrow+8)*68 + c] = f2tf(p10); sP[(mrow+8)*68 + c+1] = f2tf(p11);
        }
        ls0 += __shfl_xor_sync(0xffffffffu, ls0, 1);
        ls0 += __shfl_xor_sync(0xffffffffu, ls0, 2);
        ls1 += __shfl_xor_sync(0xffffffffu, ls1, 1);
        ls1 += __shfl_xor_sync(0xffffffffu, ls1, 2);
        l0 = l0*al0 + ls0; l1 = l1*al1 + ls1;
        #pragma unroll
        for (int j = 0; j < 16; j++) { o[j][0]*=al0; o[j][1]*=al0; o[j][2]*=al1; o[j][3]*=al1; }
        __syncwarp();

        #pragma unroll
        for (int kb = 0; kb < 64; kb += 8) {
            uint32_t a0 = sP[(mrow  )*68 + kb + t],   a1 = sP[(mrow+8)*68 + kb + t];
            uint32_t a2 = sP[(mrow  )*68 + kb + t+4], a3 = sP[(mrow+8)*68 + kb + t+4];
            #pragma unroll
            for (int j = 0; j < 16; j++) {
                uint32_t b0 = f2tf(cKV[(kb+t  )*132 + j*8+g]);
                uint32_t b1 = f2tf(cKV[(kb+t+4)*132 + j*8+g]);
                mma8(o[j][0],o[j][1],o[j][2],o[j][3], a0,a1,a2,a3, b0,b1);
            }
        }
    }

    float inv0 = 1.f/l0, inv1 = 1.f/l1;
    int grow0 = q0 + mrow;
    #pragma unroll
    for (int j = 0; j < 16; j++) {
        int col = j*8 + 2*t;
        size_t base0 = ((size_t)((b*SQ+grow0  )*NH + h))*128 + col;
        size_t base1 = ((size_t)((b*SQ+grow0+8)*NH + h))*128 + col;
        *(float2*)&vlat[base0] = make_float2(o[j][0]*inv0, o[j][1]*inv0);
        *(float2*)&vlat[base1] = make_float2(o[j][2]*inv1, o[j][3]*inv1);
    }
}

// ---------- launch ----------
extern "C" void kernel_launch(void* const* d_in, const int* in_sizes, int n_in,
                              void* d_out, int out_size)
{
    const float* h_ptr     = (const float*)d_in[0];
    const float* wq_a_w    = (const float*)d_in[2];
    const float* wq_a_b    = (const float*)d_in[3];
    const float* q_norm_w  = (const float*)d_in[4];
    const float* wq_b_w    = (const float*)d_in[5];
    const float* wq_b_b    = (const float*)d_in[6];
    const float* wkv_a_w   = (const float*)d_in[7];
    const float* wkv_a_b   = (const float*)d_in[8];
    const float* kv_norm_w = (const float*)d_in[9];
    const float* wkv_b_w   = (const float*)d_in[10];
    const float* wo_w      = (const float*)d_in[11];
    const float* wo_b      = (const float*)d_in[12];
    float* out = (float*)d_out;

    float *projcat, *qlat, *kvn, *qkv, *vlat, *wc, *biasc, *wo2, *wcat, *bcat;
    cudaGetSymbolAddress((void**)&projcat, g_projcat);
    cudaGetSymbolAddress((void**)&qlat,  g_qlat);
    cudaGetSymbolAddress((void**)&kvn,   g_kvn);
    cudaGetSymbolAddress((void**)&qkv,   g_qkv);
    cudaGetSymbolAddress((void**)&vlat,  g_vlat);
    cudaGetSymbolAddress((void**)&wc,    g_wc);
    cudaGetSymbolAddress((void**)&biasc, g_biasc);
    cudaGetSymbolAddress((void**)&wo2,   g_wo2);
    cudaGetSymbolAddress((void**)&wcat,  g_wcat);
    cudaGetSymbolAddress((void**)&bcat,  g_bcat);

    const int gsm = 2*128*36*4*2;                 // 73728
    const int asm_ = 2*64*132*4 + 64*68*4;        // 84992
    cudaFuncSetAttribute(tgemm2,  cudaFuncAttributeMaxDynamicSharedMemorySize, gsm);
    cudaFuncSetAttribute(attn_tc, cudaFuncAttributeMaxDynamicSharedMemorySize, asm_);

    prep_wcat<<<384, 256>>>(wq_a_w, wq_a_b, wkv_a_w, wkv_a_b, wcat, bcat);
    prep_wc_kernel<<<NH*DLKV, DLQ>>>(wq_b_w, wq_b_b, wkv_b_w, wc, biasc);
    prep_wo2_kernel<<<dim3(DIM, NH), DLKV>>>(wo_w, wkv_b_w, wo2);

    // merged latent projections: [8192,1024] x [384,1024]^T
    tgemm2<<<dim3(3, NTOK/128), 256, gsm>>>(h_ptr, wcat, bcat, projcat, NTOK, 384, DIM);
    rms_kernel<<<NTOK, 128>>>(projcat, 384, 0,   q_norm_w,  qlat, DLQ);
    rms_kernel<<<NTOK, 128>>>(projcat, 384, 256, kv_norm_w, kvn,  DLKV);

    // absorbed q -> latent-kv: [8192,256] x [2048,256]^T
    tgemm2<<<dim3(16, NTOK/128), 256, gsm>>>(qlat, wc, biasc, qkv, NTOK, NH*DLKV, DLQ);

    attn_tc<<<dim3(SQ/64, NH, BB), 128, asm_>>>(qkv, kvn, vlat);

    // absorbed v -> out: [8192,2048] x [1024,2048]^T
    tgemm2<<<dim3(8, NTOK/128), 256, gsm>>>(vlat, wo2, wo_b, out, NTOK, DIM, NH*DLKV);
}

// round 6
// speedup vs baseline: 3.8814x; 1.1861x over previous
#include <cuda_runtime.h>
#include <cstdint>

#define SQ   2048
#define BB   4
#define DIM  1024
#define NH   16
#define NDQK 20
#define NDV  64
#define DLQ  256
#define DLKV 128
#define NTOK (BB*SQ)

__device__ float g_projcat[(size_t)NTOK*384];
__device__ float g_qlat[NTOK*DLQ];
__device__ float g_kvn [NTOK*DLKV];
__device__ float g_qkv [(size_t)NTOK*NH*DLKV];
__device__ float g_vlat[(size_t)NTOK*NH*DLKV];
__device__ float g_wc  [NH*DLKV*DLQ];
__device__ float g_biasc[NH*DLKV];
__device__ float g_wo2 [DIM*NH*DLKV];
__device__ float g_wcat[384*DIM];
__device__ float g_bcat[384];

// ======================= helpers =======================
__device__ __forceinline__ uint32_t f2tf(float f){
    uint32_t u; asm("cvt.rna.tf32.f32 %0, %1;" : "=r"(u) : "f"(f)); return u;
}
__device__ __forceinline__ float rnd(float f){ return __uint_as_float(f2tf(f)); }
__device__ __forceinline__ void mma8(float&c0,float&c1,float&c2,float&c3,
    uint32_t a0,uint32_t a1,uint32_t a2,uint32_t a3,uint32_t b0,uint32_t b1){
    asm volatile("mma.sync.aligned.m16n8k8.row.col.f32.tf32.tf32.f32 "
        "{%0,%1,%2,%3}, {%4,%5,%6,%7}, {%8,%9}, {%0,%1,%2,%3};"
        : "+f"(c0),"+f"(c1),"+f"(c2),"+f"(c3)
        : "r"(a0),"r"(a1),"r"(a2),"r"(a3),"r"(b0),"r"(b1));
}
__device__ __forceinline__ uint32_t smem_u32(const void* p){
    uint32_t a;
    asm("{ .reg .u64 t; cvta.to.shared.u64 t, %1; cvt.u32.u64 %0, t; }" : "=r"(a) : "l"(p));
    return a;
}
__device__ __forceinline__ void cp16(uint32_t dst, const void* src){
    asm volatile("cp.async.cg.shared.global [%0], [%1], 16;" :: "r"(dst), "l"(src));
}
__device__ __forceinline__ void cp_commit(){ asm volatile("cp.async.commit_group;" ::: "memory"); }
template<int NW> __device__ __forceinline__ void cp_wait(){
    asm volatile("cp.async.wait_group %0;" :: "n"(NW) : "memory");
}
__device__ __forceinline__ uint32_t ldb(const float* p){ return __float_as_uint(*p); }

// ---------- weight prep (outputs tf32-pre-rounded) ----------
__global__ void prep_wcat(const float* __restrict__ wq_a_w, const float* __restrict__ wq_a_b,
                          const float* __restrict__ wkv_a_w, const float* __restrict__ wkv_a_b,
                          float* __restrict__ wcat, float* __restrict__ bcat){
    int n = blockIdx.x;
    const float* src = (n < 256) ? (wq_a_w + (size_t)n*DIM) : (wkv_a_w + (size_t)(n-256)*DIM);
    for (int k = threadIdx.x; k < DIM; k += 256) wcat[(size_t)n*DIM + k] = rnd(src[k]);
    if (threadIdx.x == 0) bcat[n] = (n < 256) ? wq_a_b[n] : wkv_a_b[n-256];
}
__global__ void prep_wc_kernel(const float* __restrict__ wq_b_w,
                               const float* __restrict__ wq_b_b,
                               const float* __restrict__ wkv_b_w,
                               float* __restrict__ wc, float* __restrict__ biasc) {
    int hc = blockIdx.x, h = hc >> 7, c = hc & 127, l = threadIdx.x;
    float acc = 0.f, accb = 0.f;
    #pragma unroll
    for (int q = 0; q < NDQK; q++) {
        float kb = wkv_b_w[(size_t)(h*(NDQK+NDV) + q)*DLKV + c];
        acc  = fmaf(kb, wq_b_w[(size_t)(h*NDQK + q)*DLQ + l], acc);
        accb = fmaf(kb, wq_b_b[h*NDQK + q], accb);
    }
    wc[(size_t)hc*DLQ + l] = rnd(acc);
    if (l == 0) biasc[hc] = accb;
}
__global__ void prep_wo2_kernel(const float* __restrict__ wo_w,
                                const float* __restrict__ wkv_b_w,
                                float* __restrict__ wo2) {
    int d = blockIdx.x, h = blockIdx.y, c = threadIdx.x;
    float acc = 0.f;
    #pragma unroll 8
    for (int v = 0; v < NDV; v++)
        acc = fmaf(wo_w[(size_t)d*(NH*NDV) + h*NDV + v],
                   wkv_b_w[(size_t)(h*(NDQK+NDV) + NDQK + v)*DLKV + c], acc);
    wo2[(size_t)d*(NH*DLKV) + h*DLKV + c] = rnd(acc);
}

// ---------- RMSNorm (strided input, rounded output) ----------
__global__ void rms_kernel(const float* __restrict__ in, int ld, int off,
                           const float* __restrict__ w, float* __restrict__ out, int N) {
    int row = blockIdx.x;
    const float* x = in + (size_t)row*ld + off;
    float ss = 0.f;
    for (int i = threadIdx.x; i < N; i += 128) { float v = x[i]; ss = fmaf(v, v, ss); }
    #pragma unroll
    for (int d = 16; d; d >>= 1) ss += __shfl_xor_sync(0xffffffffu, ss, d);
    __shared__ float red[4];
    if ((threadIdx.x & 31) == 0) red[threadIdx.x >> 5] = ss;
    __syncthreads();
    float r = rsqrtf((red[0]+red[1]+red[2]+red[3]) / (float)N + 1e-6f);
    for (int i = threadIdx.x; i < N; i += 128)
        out[(size_t)row*N + i] = rnd(x[i] * r * w[i]);
}

// ---------- tf32 mma GEMM, cp.async 2-stage, 128x128 tile, BK=32 ----------
// C[M,N] = A[M,K] @ B[N,K]^T + bias[N]. CVTA: convert A frags; ROUND: round C.
template<bool CVTA, bool ROUND>
__global__ __launch_bounds__(256, 2) void tgemm2(
    const float* __restrict__ A, const float* __restrict__ Bm,
    const float* __restrict__ bias, float* __restrict__ C,
    int M, int N, int K)
{
    extern __shared__ float smem[];
    float* sA = smem;                  // [2][128][36]
    float* sB = smem + 2*128*36;       // [2][128][36]

    const int mt = blockIdx.y*128, nt = blockIdx.x*128;
    const int tid = threadIdx.x, w = tid>>5, lane = tid&31;
    const int g = lane>>2, t = lane&3;
    const int wm = (w&3)*32, wn = (w>>2)*64;

    float acc[2][8][4];
    #pragma unroll
    for (int i=0;i<2;i++)
        #pragma unroll
        for (int j=0;j<8;j++){ acc[i][j][0]=0.f; acc[i][j][1]=0.f; acc[i][j][2]=0.f; acc[i][j][3]=0.f; }

    const int NC = K >> 5;
    {
        #pragma unroll
        for (int s2=0;s2<4;s2++){
            int v = tid + s2*256, r = v>>3, c4 = (v&7)<<2;
            cp16(smem_u32(&sA[r*36 + c4]), &A [(size_t)(mt+r)*K + c4]);
            cp16(smem_u32(&sB[r*36 + c4]), &Bm[(size_t)(nt+r)*K + c4]);
        }
        cp_commit();
    }
    for (int i=0;i<NC;i++){
        const int st = i&1;
        __syncthreads();
        if (i+1 < NC){
            const int k0 = (i+1) << 5;
            float* dA = sA + (1-st)*128*36;
            float* dB = sB + (1-st)*128*36;
            #pragma unroll
            for (int s2=0;s2<4;s2++){
                int v = tid + s2*256, r = v>>3, c4 = (v&7)<<2;
                cp16(smem_u32(&dA[r*36 + c4]), &A [(size_t)(mt+r)*K + k0 + c4]);
                cp16(smem_u32(&dB[r*36 + c4]), &Bm[(size_t)(nt+r)*K + k0 + c4]);
            }
            cp_commit();
            cp_wait<1>();
        } else {
            cp_wait<0>();
        }
        __syncthreads();
        const float* cA = sA + st*128*36;
        const float* cB = sB + st*128*36;
        #pragma unroll
        for (int kk=0; kk<32; kk+=8){
            uint32_t af[2][4], bf[8][2];
            #pragma unroll
            for (int ii=0;ii<2;ii++){
                int mb = wm + ii*16;
                if (CVTA){
                    af[ii][0]=f2tf(cA[(mb+g  )*36+kk+t]);   af[ii][1]=f2tf(cA[(mb+g+8)*36+kk+t]);
                    af[ii][2]=f2tf(cA[(mb+g  )*36+kk+t+4]); af[ii][3]=f2tf(cA[(mb+g+8)*36+kk+t+4]);
                } else {
                    af[ii][0]=ldb(&cA[(mb+g  )*36+kk+t]);   af[ii][1]=ldb(&cA[(mb+g+8)*36+kk+t]);
                    af[ii][2]=ldb(&cA[(mb+g  )*36+kk+t+4]); af[ii][3]=ldb(&cA[(mb+g+8)*36+kk+t+4]);
                }
            }
            #pragma unroll
            for (int j=0;j<8;j++){
                int nb = wn + j*8;
                bf[j][0]=ldb(&cB[(nb+g)*36+kk+t]); bf[j][1]=ldb(&cB[(nb+g)*36+kk+t+4]);
            }
            #pragma unroll
            for (int ii=0;ii<2;ii++)
                #pragma unroll
                for (int j=0;j<8;j++)
                    mma8(acc[ii][j][0],acc[ii][j][1],acc[ii][j][2],acc[ii][j][3],
                         af[ii][0],af[ii][1],af[ii][2],af[ii][3],bf[j][0],bf[j][1]);
        }
    }
    #pragma unroll
    for (int ii=0;ii<2;ii++){
        int row0 = mt + wm + ii*16 + g, row1 = row0 + 8;
        #pragma unroll
        for (int j=0;j<8;j++){
            int col = nt + wn + j*8 + 2*t;
            float b0v = bias[col], b1v = bias[col+1];
            float o00 = acc[ii][j][0]+b0v, o01 = acc[ii][j][1]+b1v;
            float o10 = acc[ii][j][2]+b0v, o11 = acc[ii][j][3]+b1v;
            if (ROUND){ o00=rnd(o00); o01=rnd(o01); o10=rnd(o10); o11=rnd(o11); }
            *(float2*)&C[(size_t)row0*N + col] = make_float2(o00, o01);
            *(float2*)&C[(size_t)row1*N + col] = make_float2(o10, o11);
        }
    }
}

// ---------- flash attention, cp.async double-buffered KV, no inner-loop cvt ----------
__global__ __launch_bounds__(128, 2) void attn_tc(
    const float* __restrict__ qkv, const float* __restrict__ kvn,
    float* __restrict__ vlat)
{
    extern __shared__ float smf[];
    float*    sKV = smf;                          // [2][64][132] pre-rounded fp32
    uint32_t* sP  = (uint32_t*)(smf + 2*64*132);  // [64][68] tf32 bits

    const int qt = (int)gridDim.x - 1 - (int)blockIdx.x;
    const int h = blockIdx.y, b = blockIdx.z;
    const int tid = threadIdx.x, lane = tid & 31;
    const int g = lane >> 2, t = lane & 3;
    const int q0 = qt*64;
    const int mrow = (tid >> 5)*16 + g;
    const float scale = 0.22360679774997896f;

    // prefetch KV tile 0
    {
        #pragma unroll
        for (int s2=0;s2<16;s2++){
            int v = tid + s2*128, r = v>>5, c4 = (v&31)<<2;
            cp16(smem_u32(&sKV[r*132 + c4]), &kvn[((size_t)(b*SQ + r))*128 + c4]);
        }
        cp_commit();
    }
    // Q fragments straight from gmem (qkv is pre-rounded tf32 bits)
    uint32_t qf[16][4];
    {
        const float* qb = &qkv[((size_t)((b*SQ + q0)*NH + h))*128];
        const size_t rs = (size_t)NH*128;
        #pragma unroll
        for (int kk = 0; kk < 16; kk++) {
            qf[kk][0] = ldb(qb + (size_t)(mrow  )*rs + kk*8 + t);
            qf[kk][1] = ldb(qb + (size_t)(mrow+8)*rs + kk*8 + t);
            qf[kk][2] = ldb(qb + (size_t)(mrow  )*rs + kk*8 + t + 4);
            qf[kk][3] = ldb(qb + (size_t)(mrow+8)*rs + kk*8 + t + 4);
        }
    }

    float o[16][4];
    #pragma unroll
    for (int j = 0; j < 16; j++) { o[j][0]=0.f; o[j][1]=0.f; o[j][2]=0.f; o[j][3]=0.f; }
    float m0=-1e30f, m1=-1e30f, l0=0.f, l1=0.f;

    for (int kt = 0; kt <= qt; kt++) {
        const int st = kt & 1;
        __syncthreads();
        if (kt < qt) {
            const int k0n = (kt+1)*64;
            float* dst = sKV + (1-st)*64*132;
            #pragma unroll
            for (int s2=0;s2<16;s2++){
                int v = tid + s2*128, r = v>>5, c4 = (v&31)<<2;
                cp16(smem_u32(&dst[r*132 + c4]), &kvn[((size_t)(b*SQ + k0n + r))*128 + c4]);
            }
            cp_commit();
            cp_wait<1>();
        } else {
            cp_wait<0>();
        }
        __syncthreads();
        const float* cKV = sKV + st*64*132;
        const int k0 = kt*64;

        float s[8][4];
        #pragma unroll
        for (int j = 0; j < 8; j++) { s[j][0]=0.f; s[j][1]=0.f; s[j][2]=0.f; s[j][3]=0.f; }
        #pragma unroll
        for (int kk = 0; kk < 16; kk++) {
            #pragma unroll
            for (int j = 0; j < 8; j++) {
                uint32_t b0 = ldb(&cKV[(j*8+g)*132 + kk*8 + t]);
                uint32_t b1 = ldb(&cKV[(j*8+g)*132 + kk*8 + t + 4]);
                mma8(s[j][0],s[j][1],s[j][2],s[j][3], qf[kk][0],qf[kk][1],qf[kk][2],qf[kk][3], b0,b1);
            }
        }

        const bool diag = (kt == qt);
        const int grow0 = q0 + mrow, grow1 = grow0 + 8;
        float mx0=-1e30f, mx1=-1e30f;
        #pragma unroll
        for (int j = 0; j < 8; j++) {
            int c = k0 + j*8 + 2*t;
            #pragma unroll
            for (int e = 0; e < 2; e++) {
                float v0 = s[j][e]*scale, v1 = s[j][2+e]*scale;
                if (diag && (c+e) > grow0) v0 = -1e30f;
                if (diag && (c+e) > grow1) v1 = -1e30f;
                s[j][e] = v0; s[j][2+e] = v1;
                mx0 = fmaxf(mx0, v0); mx1 = fmaxf(mx1, v1);
            }
        }
        mx0 = fmaxf(mx0, __shfl_xor_sync(0xffffffffu, mx0, 1));
        mx0 = fmaxf(mx0, __shfl_xor_sync(0xffffffffu, mx0, 2));
        mx1 = fmaxf(mx1, __shfl_xor_sync(0xffffffffu, mx1, 1));
        mx1 = fmaxf(mx1, __shfl_xor_sync(0xffffffffu, mx1, 2));
        float nm0 = fmaxf(m0, mx0), nm1 = fmaxf(m1, mx1);
        float al0 = __expf(m0 - nm0), al1 = __expf(m1 - nm1);
        m0 = nm0; m1 = nm1;
        float ls0 = 0.f, ls1 = 0.f;
        #pragma unroll
        for (int j = 0; j < 8; j++) {
            float p00 = __expf(s[j][0]-nm0), p01 = __expf(s[j][1]-nm0);
            float p10 = __expf(s[j][2]-nm1), p11 = __expf(s[j][3]-nm1);
            ls0 += p00 + p01; ls1 += p10 + p11;
            int c = j*8 + 2*t;
            sP[(mrow  )*68 + c] = f2tf(p00); sP[(mrow  )*68 + c+1] = f2tf(p01);
            sP[(mrow+8)*68 + c] = f2tf(p10); sP[(mrow+8)*68 + c+1] = f2tf(p11);
        }
        ls0 += __shfl_xor_sync(0xffffffffu, ls0, 1);
        ls0 += __shfl_xor_sync(0xffffffffu, ls0, 2);
        ls1 += __shfl_xor_sync(0xffffffffu, ls1, 1);
        ls1 += __shfl_xor_sync(0xffffffffu, ls1, 2);
        l0 = l0*al0 + ls0; l1 = l1*al1 + ls1;
        #pragma unroll
        for (int j = 0; j < 16; j++) { o[j][0]*=al0; o[j][1]*=al0; o[j][2]*=al1; o[j][3]*=al1; }
        __syncwarp();

        #pragma unroll
        for (int kb = 0; kb < 64; kb += 8) {
            uint32_t a0 = sP[(mrow  )*68 + kb + t],   a1 = sP[(mrow+8)*68 + kb + t];
            uint32_t a2 = sP[(mrow  )*68 + kb + t+4], a3 = sP[(mrow+8)*68 + kb + t+4];
            #pragma unroll
            for (int j = 0; j < 16; j++) {
                uint32_t b0 = ldb(&cKV[(kb+t  )*132 + j*8+g]);
                uint32_t b1 = ldb(&cKV[(kb+t+4)*132 + j*8+g]);
                mma8(o[j][0],o[j][1],o[j][2],o[j][3], a0,a1,a2,a3, b0,b1);
            }
        }
    }

    float inv0 = 1.f/l0, inv1 = 1.f/l1;
    int grow0 = q0 + mrow;
    #pragma unroll
    for (int j = 0; j < 16; j++) {
        int col = j*8 + 2*t;
        size_t base0 = ((size_t)((b*SQ+grow0  )*NH + h))*128 + col;
        size_t base1 = ((size_t)((b*SQ+grow0+8)*NH + h))*128 + col;
        *(float2*)&vlat[base0] = make_float2(rnd(o[j][0]*inv0), rnd(o[j][1]*inv0));
        *(float2*)&vlat[base1] = make_float2(rnd(o[j][2]*inv1), rnd(o[j][3]*inv1));
    }
}

// ---------- launch ----------
extern "C" void kernel_launch(void* const* d_in, const int* in_sizes, int n_in,
                              void* d_out, int out_size)
{
    const float* h_ptr     = (const float*)d_in[0];
    const float* wq_a_w    = (const float*)d_in[2];
    const float* wq_a_b    = (const float*)d_in[3];
    const float* q_norm_w  = (const float*)d_in[4];
    const float* wq_b_w    = (const float*)d_in[5];
    const float* wq_b_b    = (const float*)d_in[6];
    const float* wkv_a_w   = (const float*)d_in[7];
    const float* wkv_a_b   = (const float*)d_in[8];
    const float* kv_norm_w = (const float*)d_in[9];
    const float* wkv_b_w   = (const float*)d_in[10];
    const float* wo_w      = (const float*)d_in[11];
    const float* wo_b      = (const float*)d_in[12];
    float* out = (float*)d_out;

    float *projcat, *qlat, *kvn, *qkv, *vlat, *wc, *biasc, *wo2, *wcat, *bcat;
    cudaGetSymbolAddress((void**)&projcat, g_projcat);
    cudaGetSymbolAddress((void**)&qlat,  g_qlat);
    cudaGetSymbolAddress((void**)&kvn,   g_kvn);
    cudaGetSymbolAddress((void**)&qkv,   g_qkv);
    cudaGetSymbolAddress((void**)&vlat,  g_vlat);
    cudaGetSymbolAddress((void**)&wc,    g_wc);
    cudaGetSymbolAddress((void**)&biasc, g_biasc);
    cudaGetSymbolAddress((void**)&wo2,   g_wo2);
    cudaGetSymbolAddress((void**)&wcat,  g_wcat);
    cudaGetSymbolAddress((void**)&bcat,  g_bcat);

    const int gsm = 2*128*36*4*2;                 // 73728
    const int asm_ = 2*64*132*4 + 64*68*4;        // 84992
    cudaFuncSetAttribute((tgemm2<true,false>),  cudaFuncAttributeMaxDynamicSharedMemorySize, gsm);
    cudaFuncSetAttribute((tgemm2<false,true>),  cudaFuncAttributeMaxDynamicSharedMemorySize, gsm);
    cudaFuncSetAttribute((tgemm2<false,false>), cudaFuncAttributeMaxDynamicSharedMemorySize, gsm);
    cudaFuncSetAttribute(attn_tc, cudaFuncAttributeMaxDynamicSharedMemorySize, asm_);

    prep_wcat<<<384, 256>>>(wq_a_w, wq_a_b, wkv_a_w, wkv_a_b, wcat, bcat);
    prep_wc_kernel<<<NH*DLKV, DLQ>>>(wq_b_w, wq_b_b, wkv_b_w, wc, biasc);
    prep_wo2_kernel<<<dim3(DIM, NH), DLKV>>>(wo_w, wkv_b_w, wo2);

    // merged latent projections: [8192,1024] x [384,1024]^T (A=h needs cvt)
    tgemm2<true,false><<<dim3(3, NTOK/128), 256, gsm>>>(h_ptr, wcat, bcat, projcat, NTOK, 384, DIM);
    rms_kernel<<<NTOK, 128>>>(projcat, 384, 0,   q_norm_w,  qlat, DLQ);
    rms_kernel<<<NTOK, 128>>>(projcat, 384, 256, kv_norm_w, kvn,  DLKV);

    // absorbed q -> latent-kv: [8192,256] x [2048,256]^T (round output for attention)
    tgemm2<false,true><<<dim3(16, NTOK/128), 256, gsm>>>(qlat, wc, biasc, qkv, NTOK, NH*DLKV, DLQ);

    attn_tc<<<dim3(SQ/64, NH, BB), 128, asm_>>>(qkv, kvn, vlat);

    // absorbed v -> out: [8192,2048] x [1024,2048]^T
    tgemm2<false,false><<<dim3(8, NTOK/128), 256, gsm>>>(vlat, wo2, wo_b, out, NTOK, DIM, NH*DLKV);
}

// round 7
// speedup vs baseline: 4.4232x; 1.1396x over previous
#include <cuda_runtime.h>
#include <cstdint>

#define SQ   2048
#define BB   4
#define DIM  1024
#define NH   16
#define NDQK 20
#define NDV  64
#define DLQ  256
#define DLKV 128
#define NTOK (BB*SQ)

__device__ float g_hrnd[(size_t)NTOK*DIM];
__device__ float g_projcat[(size_t)NTOK*384];
__device__ float g_qlat[NTOK*DLQ];
__device__ float g_kvn [NTOK*DLKV];
__device__ float g_qkv [(size_t)NTOK*NH*DLKV];
__device__ float g_vlat[(size_t)NTOK*NH*DLKV];
__device__ float g_wc  [NH*DLKV*DLQ];
__device__ float g_biasc[NH*DLKV];
__device__ float g_wo2 [DIM*NH*DLKV];
__device__ float g_wcat[384*DIM];
__device__ float g_bcat[384];

// ======================= helpers =======================
__device__ __forceinline__ uint32_t f2tf(float f){
    uint32_t u; asm("cvt.rna.tf32.f32 %0, %1;" : "=r"(u) : "f"(f)); return u;
}
__device__ __forceinline__ float rnd(float f){ return __uint_as_float(f2tf(f)); }
__device__ __forceinline__ void mma8(float&c0,float&c1,float&c2,float&c3,
    uint32_t a0,uint32_t a1,uint32_t a2,uint32_t a3,uint32_t b0,uint32_t b1){
    asm volatile("mma.sync.aligned.m16n8k8.row.col.f32.tf32.tf32.f32 "
        "{%0,%1,%2,%3}, {%4,%5,%6,%7}, {%8,%9}, {%0,%1,%2,%3};"
        : "+f"(c0),"+f"(c1),"+f"(c2),"+f"(c3)
        : "r"(a0),"r"(a1),"r"(a2),"r"(a3),"r"(b0),"r"(b1));
}
__device__ __forceinline__ void ldsm4(uint32_t&r0,uint32_t&r1,uint32_t&r2,uint32_t&r3,uint32_t a){
    asm volatile("ldmatrix.sync.aligned.m8n8.x4.shared.b16 {%0,%1,%2,%3}, [%4];"
        : "=r"(r0),"=r"(r1),"=r"(r2),"=r"(r3) : "r"(a));
}
__device__ __forceinline__ uint32_t smem_u32(const void* p){
    uint32_t a;
    asm("{ .reg .u64 t; cvta.to.shared.u64 t, %1; cvt.u32.u64 %0, t; }" : "=r"(a) : "l"(p));
    return a;
}
__device__ __forceinline__ void cp16(uint32_t dst, const void* src){
    asm volatile("cp.async.cg.shared.global [%0], [%1], 16;" :: "r"(dst), "l"(src));
}
__device__ __forceinline__ void cp_commit(){ asm volatile("cp.async.commit_group;" ::: "memory"); }
template<int NW> __device__ __forceinline__ void cp_wait(){
    asm volatile("cp.async.wait_group %0;" :: "n"(NW) : "memory");
}
__device__ __forceinline__ uint32_t ldb(const float* p){ return __float_as_uint(*p); }

// ---------- prep ----------
__global__ void round_copy(const float* __restrict__ in, float* __restrict__ out){
    size_t i = ((size_t)blockIdx.x*256 + threadIdx.x)*4;
    float4 v = *(const float4*)&in[i];
    v.x=rnd(v.x); v.y=rnd(v.y); v.z=rnd(v.z); v.w=rnd(v.w);
    *(float4*)&out[i] = v;
}
__global__ void prep_wcat(const float* __restrict__ wq_a_w, const float* __restrict__ wq_a_b,
                          const float* __restrict__ wkv_a_w, const float* __restrict__ wkv_a_b,
                          float* __restrict__ wcat, float* __restrict__ bcat){
    int n = blockIdx.x;
    const float* src = (n < 256) ? (wq_a_w + (size_t)n*DIM) : (wkv_a_w + (size_t)(n-256)*DIM);
    for (int k = threadIdx.x; k < DIM; k += 256) wcat[(size_t)n*DIM + k] = rnd(src[k]);
    if (threadIdx.x == 0) bcat[n] = (n < 256) ? wq_a_b[n] : wkv_a_b[n-256];
}
__global__ void prep_wc_kernel(const float* __restrict__ wq_b_w,
                               const float* __restrict__ wq_b_b,
                               const float* __restrict__ wkv_b_w,
                               float* __restrict__ wc, float* __restrict__ biasc) {
    int hc = blockIdx.x, h = hc >> 7, c = hc & 127, l = threadIdx.x;
    float acc = 0.f, accb = 0.f;
    #pragma unroll
    for (int q = 0; q < NDQK; q++) {
        float kb = wkv_b_w[(size_t)(h*(NDQK+NDV) + q)*DLKV + c];
        acc  = fmaf(kb, wq_b_w[(size_t)(h*NDQK + q)*DLQ + l], acc);
        accb = fmaf(kb, wq_b_b[h*NDQK + q], accb);
    }
    wc[(size_t)hc*DLQ + l] = rnd(acc);
    if (l == 0) biasc[hc] = accb;
}
__global__ void prep_wo2_kernel(const float* __restrict__ wo_w,
                                const float* __restrict__ wkv_b_w,
                                float* __restrict__ wo2) {
    int d = blockIdx.x, h = blockIdx.y, c = threadIdx.x;
    float acc = 0.f;
    #pragma unroll 8
    for (int v = 0; v < NDV; v++)
        acc = fmaf(wo_w[(size_t)d*(NH*NDV) + h*NDV + v],
                   wkv_b_w[(size_t)(h*(NDQK+NDV) + NDQK + v)*DLKV + c], acc);
    wo2[(size_t)d*(NH*DLKV) + h*DLKV + c] = rnd(acc);
}

// ---------- RMSNorm (strided input, rounded output) ----------
__global__ void rms_kernel(const float* __restrict__ in, int ld, int off,
                           const float* __restrict__ w, float* __restrict__ out, int N) {
    int row = blockIdx.x;
    const float* x = in + (size_t)row*ld + off;
    float ss = 0.f;
    for (int i = threadIdx.x; i < N; i += 128) { float v = x[i]; ss = fmaf(v, v, ss); }
    #pragma unroll
    for (int d = 16; d; d >>= 1) ss += __shfl_xor_sync(0xffffffffu, ss, d);
    __shared__ float red[4];
    if ((threadIdx.x & 31) == 0) red[threadIdx.x >> 5] = ss;
    __syncthreads();
    float r = rsqrtf((red[0]+red[1]+red[2]+red[3]) / (float)N + 1e-6f);
    for (int i = threadIdx.x; i < N; i += 128)
        out[(size_t)row*N + i] = rnd(x[i] * r * w[i]);
}

// ---------- tf32 mma GEMM, cp.async 2-stage, ldmatrix fragments ----------
// C[M,N] = A[M,K] @ B[N,K]^T + bias[N]; inputs pre-rounded to tf32.
template<bool ROUND>
__global__ __launch_bounds__(256, 2) void tgemm2(
    const float* __restrict__ A, const float* __restrict__ Bm,
    const float* __restrict__ bias, float* __restrict__ C,
    int M, int N, int K)
{
    extern __shared__ float smem[];
    float* sA = smem;                  // [2][128][36]
    float* sB = smem + 2*128*36;       // [2][128][36]

    const int mt = blockIdx.y*128, nt = blockIdx.x*128;
    const int tid = threadIdx.x, w = tid>>5, lane = tid&31;
    const int g = lane>>2, t = lane&3;
    const int wm = (w&3)*32, wn = (w>>2)*64;
    const int mat = lane>>3, r8 = lane&7;
    const int matr = mat&1, matc = mat>>1;

    const uint32_t sAu = smem_u32(sA), sBu = smem_u32(sB);
    // ldmatrix per-lane byte offsets (A: row += matr*8, col += matc*4; B: row += matc*8, col += matr*4)
    const uint32_t aoff0 = (uint32_t)(((wm + matr*8 + r8)*36 + matc*4)*4);
    const uint32_t boff0 = (uint32_t)(((wn + matc*8 + r8)*36 + matr*4)*4);

    float acc[2][8][4];
    #pragma unroll
    for (int i=0;i<2;i++)
        #pragma unroll
        for (int j=0;j<8;j++){ acc[i][j][0]=0.f; acc[i][j][1]=0.f; acc[i][j][2]=0.f; acc[i][j][3]=0.f; }

    const int NC = K >> 5;
    {
        #pragma unroll
        for (int s2=0;s2<4;s2++){
            int v = tid + s2*256, r = v>>3, c4 = (v&7)<<2;
            cp16(smem_u32(&sA[r*36 + c4]), &A [(size_t)(mt+r)*K + c4]);
            cp16(smem_u32(&sB[r*36 + c4]), &Bm[(size_t)(nt+r)*K + c4]);
        }
        cp_commit();
    }
    for (int i=0;i<NC;i++){
        const int st = i&1;
        __syncthreads();
        if (i+1 < NC){
            const int k0 = (i+1) << 5;
            float* dA = sA + (1-st)*128*36;
            float* dB = sB + (1-st)*128*36;
            #pragma unroll
            for (int s2=0;s2<4;s2++){
                int v = tid + s2*256, r = v>>3, c4 = (v&7)<<2;
                cp16(smem_u32(&dA[r*36 + c4]), &A [(size_t)(mt+r)*K + k0 + c4]);
                cp16(smem_u32(&dB[r*36 + c4]), &Bm[(size_t)(nt+r)*K + k0 + c4]);
            }
            cp_commit();
            cp_wait<1>();
        } else {
            cp_wait<0>();
        }
        __syncthreads();
        const uint32_t aB = sAu + (uint32_t)(st*128*36*4);
        const uint32_t bB = sBu + (uint32_t)(st*128*36*4);
        #pragma unroll
        for (int kk=0; kk<32; kk+=8){
            uint32_t af[2][4], bf[8][2];
            #pragma unroll
            for (int ii=0;ii<2;ii++)
                ldsm4(af[ii][0],af[ii][1],af[ii][2],af[ii][3],
                      aB + aoff0 + (uint32_t)(ii*16*36*4 + kk*4));
            #pragma unroll
            for (int p=0;p<4;p++){
                uint32_t r0,r1,r2,r3;
                ldsm4(r0,r1,r2,r3, bB + boff0 + (uint32_t)(p*16*36*4 + kk*4));
                bf[2*p][0]=r0; bf[2*p][1]=r1; bf[2*p+1][0]=r2; bf[2*p+1][1]=r3;
            }
            #pragma unroll
            for (int ii=0;ii<2;ii++)
                #pragma unroll
                for (int j=0;j<8;j++)
                    mma8(acc[ii][j][0],acc[ii][j][1],acc[ii][j][2],acc[ii][j][3],
                         af[ii][0],af[ii][1],af[ii][2],af[ii][3],bf[j][0],bf[j][1]);
        }
    }
    #pragma unroll
    for (int ii=0;ii<2;ii++){
        int row0 = mt + wm + ii*16 + g, row1 = row0 + 8;
        #pragma unroll
        for (int j=0;j<8;j++){
            int col = nt + wn + j*8 + 2*t;
            float b0v = bias[col], b1v = bias[col+1];
            float o00 = acc[ii][j][0]+b0v, o01 = acc[ii][j][1]+b1v;
            float o10 = acc[ii][j][2]+b0v, o11 = acc[ii][j][3]+b1v;
            if (ROUND){ o00=rnd(o00); o01=rnd(o01); o10=rnd(o10); o11=rnd(o11); }
            *(float2*)&C[(size_t)row0*N + col] = make_float2(o00, o01);
            *(float2*)&C[(size_t)row1*N + col] = make_float2(o10, o11);
        }
    }
}

// ---------- flash attention: ldsm S-frags, column-partitioned PV ----------
__global__ __launch_bounds__(128, 2) void attn_tc(
    const float* __restrict__ qkv, const float* __restrict__ kvn,
    float* __restrict__ vlat)
{
    extern __shared__ float smf[];
    float*    sKV = smf;                          // [2][64][132]
    uint32_t* sP  = (uint32_t*)(smf + 2*64*132);  // [64][68] tf32 bits
    float*    sAl = smf + 2*64*132 + 64*68;       // [64] alpha
    float*    sL  = sAl + 64;                     // [64] sum

    const int qt = (int)gridDim.x - 1 - (int)blockIdx.x;
    const int h = blockIdx.y, b = blockIdx.z;
    const int tid = threadIdx.x, w = tid>>5, lane = tid & 31;
    const int g = lane >> 2, t = lane & 3;
    const int mat = lane>>3, r8 = lane&7;
    const int matr = mat&1, matc = mat>>1;
    const int q0 = qt*64;
    const int mrow = w*16 + g;            // softmax row ownership
    const int wn = w*32;                  // PV column ownership
    const float scale = 0.22360679774997896f;

    const uint32_t kvu = smem_u32(sKV);
    const uint32_t pu  = smem_u32(sP);
    // K-frag (B-pattern, stride 132): row = (2p+matc)*8+r8, col = kk + matr*4
    const uint32_t koff0 = (uint32_t)(((matc*8 + r8)*132 + matr*4)*4);
    // P-frag (A-pattern, stride 68): row = mi*16 + matr*8 + r8, col = kb + matc*4
    const uint32_t poff0 = (uint32_t)(((matr*8 + r8)*68 + matc*4)*4);

    // prefetch KV tile 0
    {
        #pragma unroll
        for (int s2=0;s2<16;s2++){
            int v = tid + s2*128, r = v>>5, c4 = (v&31)<<2;
            cp16(smem_u32(&sKV[r*132 + c4]), &kvn[((size_t)(b*SQ + r))*128 + c4]);
        }
        cp_commit();
    }
    // Q fragments from gmem (pre-rounded)
    uint32_t qf[16][4];
    {
        const float* qb = &qkv[((size_t)((b*SQ + q0)*NH + h))*128];
        const size_t rs = (size_t)NH*128;
        #pragma unroll
        for (int kk = 0; kk < 16; kk++) {
            qf[kk][0] = ldb(qb + (size_t)(mrow  )*rs + kk*8 + t);
            qf[kk][1] = ldb(qb + (size_t)(mrow+8)*rs + kk*8 + t);
            qf[kk][2] = ldb(qb + (size_t)(mrow  )*rs + kk*8 + t + 4);
            qf[kk][3] = ldb(qb + (size_t)(mrow+8)*rs + kk*8 + t + 4);
        }
    }

    float o[4][4][4];   // [m-tile][n-tile(8col) within warp cols][frag]
    #pragma unroll
    for (int mi=0;mi<4;mi++)
        #pragma unroll
        for (int j=0;j<4;j++){ o[mi][j][0]=0.f; o[mi][j][1]=0.f; o[mi][j][2]=0.f; o[mi][j][3]=0.f; }
    float m0=-1e30f, m1=-1e30f, l0=0.f, l1=0.f;

    for (int kt = 0; kt <= qt; kt++) {
        const int st = kt & 1;
        __syncthreads();                 // prev tile PV done: safe to refill buffer + rewrite P
        if (kt < qt) {
            const int k0n = (kt+1)*64;
            float* dst = sKV + (1-st)*64*132;
            #pragma unroll
            for (int s2=0;s2<16;s2++){
                int v = tid + s2*128, r = v>>5, c4 = (v&31)<<2;
                cp16(smem_u32(&dst[r*132 + c4]), &kvn[((size_t)(b*SQ + k0n + r))*128 + c4]);
            }
            cp_commit();
            cp_wait<1>();
        } else {
            cp_wait<0>();
        }
        __syncthreads();
        const float* cKV = sKV + st*64*132;
        const uint32_t kB = kvu + (uint32_t)(st*64*132*4);
        const int k0 = kt*64;

        // S = Q @ K^T : warp computes its 16 rows x 64 cols
        float s[8][4];
        #pragma unroll
        for (int j = 0; j < 8; j++) { s[j][0]=0.f; s[j][1]=0.f; s[j][2]=0.f; s[j][3]=0.f; }
        #pragma unroll
        for (int kk = 0; kk < 16; kk++) {
            uint32_t bf[8][2];
            #pragma unroll
            for (int p=0;p<4;p++){
                uint32_t r0,r1,r2,r3;
                ldsm4(r0,r1,r2,r3, kB + koff0 + (uint32_t)(p*16*132*4 + kk*8*4));
                bf[2*p][0]=r0; bf[2*p][1]=r1; bf[2*p+1][0]=r2; bf[2*p+1][1]=r3;
            }
            #pragma unroll
            for (int j = 0; j < 8; j++)
                mma8(s[j][0],s[j][1],s[j][2],s[j][3], qf[kk][0],qf[kk][1],qf[kk][2],qf[kk][3],
                     bf[j][0],bf[j][1]);
        }

        // softmax (row owners)
        const bool diag = (kt == qt);
        const int grow0 = q0 + mrow, grow1 = grow0 + 8;
        float mx0=-1e30f, mx1=-1e30f;
        #pragma unroll
        for (int j = 0; j < 8; j++) {
            int c = k0 + j*8 + 2*t;
            #pragma unroll
            for (int e = 0; e < 2; e++) {
                float v0 = s[j][e]*scale, v1 = s[j][2+e]*scale;
                if (diag && (c+e) > grow0) v0 = -1e30f;
                if (diag && (c+e) > grow1) v1 = -1e30f;
                s[j][e] = v0; s[j][2+e] = v1;
                mx0 = fmaxf(mx0, v0); mx1 = fmaxf(mx1, v1);
            }
        }
        mx0 = fmaxf(mx0, __shfl_xor_sync(0xffffffffu, mx0, 1));
        mx0 = fmaxf(mx0, __shfl_xor_sync(0xffffffffu, mx0, 2));
        mx1 = fmaxf(mx1, __shfl_xor_sync(0xffffffffu, mx1, 1));
        mx1 = fmaxf(mx1, __shfl_xor_sync(0xffffffffu, mx1, 2));
        float nm0 = fmaxf(m0, mx0), nm1 = fmaxf(m1, mx1);
        float al0 = __expf(m0 - nm0), al1 = __expf(m1 - nm1);
        m0 = nm0; m1 = nm1;
        float ls0 = 0.f, ls1 = 0.f;
        #pragma unroll
        for (int j = 0; j < 8; j++) {
            float p00 = __expf(s[j][0]-nm0), p01 = __expf(s[j][1]-nm0);
            float p10 = __expf(s[j][2]-nm1), p11 = __expf(s[j][3]-nm1);
            ls0 += p00 + p01; ls1 += p10 + p11;
            int c = j*8 + 2*t;
            sP[(mrow  )*68 + c] = f2tf(p00); sP[(mrow  )*68 + c+1] = f2tf(p01);
            sP[(mrow+8)*68 + c] = f2tf(p10); sP[(mrow+8)*68 + c+1] = f2tf(p11);
        }
        ls0 += __shfl_xor_sync(0xffffffffu, ls0, 1);
        ls0 += __shfl_xor_sync(0xffffffffu, ls0, 2);
        ls1 += __shfl_xor_sync(0xffffffffu, ls1, 1);
        ls1 += __shfl_xor_sync(0xffffffffu, ls1, 2);
        l0 = l0*al0 + ls0; l1 = l1*al1 + ls1;
        if (t == 0){ sAl[mrow] = al0; sAl[mrow+8] = al1; }
        __syncthreads();                 // P + alpha visible to all warps

        // PV column-partitioned: warp owns cols [wn, wn+32) for ALL 64 rows
        float alo[4], ahi[4];
        #pragma unroll
        for (int mi=0;mi<4;mi++){ alo[mi]=sAl[mi*16+g]; ahi[mi]=sAl[mi*16+8+g]; }
        #pragma unroll
        for (int mi=0;mi<4;mi++)
            #pragma unroll
            for (int j=0;j<4;j++){
                o[mi][j][0]*=alo[mi]; o[mi][j][1]*=alo[mi];
                o[mi][j][2]*=ahi[mi]; o[mi][j][3]*=ahi[mi];
            }
        #pragma unroll
        for (int kb = 0; kb < 64; kb += 8) {
            uint32_t pf[4][4];
            #pragma unroll
            for (int mi=0;mi<4;mi++)
                ldsm4(pf[mi][0],pf[mi][1],pf[mi][2],pf[mi][3],
                      pu + poff0 + (uint32_t)(mi*16*68*4 + kb*4));
            #pragma unroll
            for (int j=0;j<4;j++){
                uint32_t b0 = ldb(&cKV[(kb+t  )*132 + wn + j*8 + g]);
                uint32_t b1 = ldb(&cKV[(kb+t+4)*132 + wn + j*8 + g]);
                #pragma unroll
                for (int mi=0;mi<4;mi++)
                    mma8(o[mi][j][0],o[mi][j][1],o[mi][j][2],o[mi][j][3],
                         pf[mi][0],pf[mi][1],pf[mi][2],pf[mi][3], b0,b1);
            }
        }
    }

    if (t == 0){ sL[mrow] = l0; sL[mrow+8] = l1; }
    __syncthreads();
    #pragma unroll
    for (int mi=0;mi<4;mi++){
        int lr0 = mi*16 + g, lr1 = lr0 + 8;
        float inv0 = 1.f/sL[lr0], inv1 = 1.f/sL[lr1];
        size_t base0 = ((size_t)((b*SQ + q0 + lr0)*NH + h))*128 + wn;
        size_t base1 = ((size_t)((b*SQ + q0 + lr1)*NH + h))*128 + wn;
        #pragma unroll
        for (int j=0;j<4;j++){
            int col = j*8 + 2*t;
            *(float2*)&vlat[base0 + col] = make_float2(rnd(o[mi][j][0]*inv0), rnd(o[mi][j][1]*inv0));
            *(float2*)&vlat[base1 + col] = make_float2(rnd(o[mi][j][2]*inv1), rnd(o[mi][j][3]*inv1));
        }
    }
}

// ---------- launch ----------
extern "C" void kernel_launch(void* const* d_in, const int* in_sizes, int n_in,
                              void* d_out, int out_size)
{
    const float* h_ptr     = (const float*)d_in[0];
    const float* wq_a_w    = (const float*)d_in[2];
    const float* wq_a_b    = (const float*)d_in[3];
    const float* q_norm_w  = (const float*)d_in[4];
    const float* wq_b_w    = (const float*)d_in[5];
    const float* wq_b_b    = (const float*)d_in[6];
    const float* wkv_a_w   = (const float*)d_in[7];
    const float* wkv_a_b   = (const float*)d_in[8];
    const float* kv_norm_w = (const float*)d_in[9];
    const float* wkv_b_w   = (const float*)d_in[10];
    const float* wo_w      = (const float*)d_in[11];
    const float* wo_b      = (const float*)d_in[12];
    float* out = (float*)d_out;

    float *hrnd, *projcat, *qlat, *kvn, *qkv, *vlat, *wc, *biasc, *wo2, *wcat, *bcat;
    cudaGetSymbolAddress((void**)&hrnd,  g_hrnd);
    cudaGetSymbolAddress((void**)&projcat, g_projcat);
    cudaGetSymbolAddress((void**)&qlat,  g_qlat);
    cudaGetSymbolAddress((void**)&kvn,   g_kvn);
    cudaGetSymbolAddress((void**)&qkv,   g_qkv);
    cudaGetSymbolAddress((void**)&vlat,  g_vlat);
    cudaGetSymbolAddress((void**)&wc,    g_wc);
    cudaGetSymbolAddress((void**)&biasc, g_biasc);
    cudaGetSymbolAddress((void**)&wo2,   g_wo2);
    cudaGetSymbolAddress((void**)&wcat,  g_wcat);
    cudaGetSymbolAddress((void**)&bcat,  g_bcat);

    const int gsm  = 2*128*36*4*2;                       // 73728
    const int asm_ = (2*64*132 + 64*68 + 128)*4;         // 85504
    cudaFuncSetAttribute((tgemm2<true>),  cudaFuncAttributeMaxDynamicSharedMemorySize, gsm);
    cudaFuncSetAttribute((tgemm2<false>), cudaFuncAttributeMaxDynamicSharedMemorySize, gsm);
    cudaFuncSetAttribute(attn_tc, cudaFuncAttributeMaxDynamicSharedMemorySize, asm_);

    round_copy<<<NTOK*DIM/1024, 256>>>(h_ptr, hrnd);
    prep_wcat<<<384, 256>>>(wq_a_w, wq_a_b, wkv_a_w, wkv_a_b, wcat, bcat);
    prep_wc_kernel<<<NH*DLKV, DLQ>>>(wq_b_w, wq_b_b, wkv_b_w, wc, biasc);
    prep_wo2_kernel<<<dim3(DIM, NH), DLKV>>>(wo_w, wkv_b_w, wo2);

    // merged latent projections: [8192,1024] x [384,1024]^T
    tgemm2<false><<<dim3(3, NTOK/128), 256, gsm>>>(hrnd, wcat, bcat, projcat, NTOK, 384, DIM);
    rms_kernel<<<NTOK, 128>>>(projcat, 384, 0,   q_norm_w,  qlat, DLQ);
    rms_kernel<<<NTOK, 128>>>(projcat, 384, 256, kv_norm_w, kvn,  DLKV);

    // absorbed q -> latent-kv: [8192,256] x [2048,256]^T (rounded for attention)
    tgemm2<true><<<dim3(16, NTOK/128), 256, gsm>>>(qlat, wc, biasc, qkv, NTOK, NH*DLKV, DLQ);

    attn_tc<<<dim3(SQ/64, NH, BB), 128, asm_>>>(qkv, kvn, vlat);

    // absorbed v -> out: [8192,2048] x [1024,2048]^T
    tgemm2<false><<<dim3(8, NTOK/128), 256, gsm>>>(vlat, wo2, wo_b, out, NTOK, DIM, NH*DLKV);
}

// round 8
// speedup vs baseline: 4.4502x; 1.0061x over previous
#include <cuda_runtime.h>
#include <cstdint>

#define SQ   2048
#define BB   4
#define DIM  1024
#define NH   16
#define NDQK 20
#define NDV  64
#define DLQ  256
#define DLKV 128
#define NTOK (BB*SQ)

__device__ float g_hrnd[(size_t)NTOK*DIM];
__device__ float g_projcat[(size_t)NTOK*384];
__device__ float g_qlat[NTOK*DLQ];
__device__ float g_kvn [NTOK*DLKV];
__device__ float g_qkv [(size_t)NTOK*NH*DLKV];
__device__ float g_vlat[(size_t)NTOK*NH*DLKV];
__device__ float g_wc  [NH*DLKV*DLQ];
__device__ float g_biasc[NH*DLKV];
__device__ float g_wo2 [DIM*NH*DLKV];
__device__ float g_wcat[384*DIM];
__device__ float g_bcat[384];

// ======================= helpers =======================
__device__ __forceinline__ uint32_t f2tf(float f){
    uint32_t u; asm("cvt.rna.tf32.f32 %0, %1;" : "=r"(u) : "f"(f)); return u;
}
__device__ __forceinline__ float rnd(float f){ return __uint_as_float(f2tf(f)); }
__device__ __forceinline__ void mma8(float&c0,float&c1,float&c2,float&c3,
    uint32_t a0,uint32_t a1,uint32_t a2,uint32_t a3,uint32_t b0,uint32_t b1){
    asm volatile("mma.sync.aligned.m16n8k8.row.col.f32.tf32.tf32.f32 "
        "{%0,%1,%2,%3}, {%4,%5,%6,%7}, {%8,%9}, {%0,%1,%2,%3};"
        : "+f"(c0),"+f"(c1),"+f"(c2),"+f"(c3)
        : "r"(a0),"r"(a1),"r"(a2),"r"(a3),"r"(b0),"r"(b1));
}
__device__ __forceinline__ void ldsm4(uint32_t&r0,uint32_t&r1,uint32_t&r2,uint32_t&r3,uint32_t a){
    asm volatile("ldmatrix.sync.aligned.m8n8.x4.shared.b16 {%0,%1,%2,%3}, [%4];"
        : "=r"(r0),"=r"(r1),"=r"(r2),"=r"(r3) : "r"(a));
}
__device__ __forceinline__ uint32_t smem_u32(const void* p){
    uint32_t a;
    asm("{ .reg .u64 t; cvta.to.shared.u64 t, %1; cvt.u32.u64 %0, t; }" : "=r"(a) : "l"(p));
    return a;
}
__device__ __forceinline__ void cp16(uint32_t dst, const void* src){
    asm volatile("cp.async.cg.shared.global [%0], [%1], 16;" :: "r"(dst), "l"(src));
}
__device__ __forceinline__ void cp_commit(){ asm volatile("cp.async.commit_group;" ::: "memory"); }
template<int NW> __device__ __forceinline__ void cp_wait(){
    asm volatile("cp.async.wait_group %0;" :: "n"(NW) : "memory");
}
__device__ __forceinline__ uint32_t ldb(const float* p){ return __float_as_uint(*p); }

// ---------- prep ----------
__global__ void round_copy(const float* __restrict__ in, float* __restrict__ out){
    size_t i = ((size_t)blockIdx.x*256 + threadIdx.x)*4;
    float4 v = *(const float4*)&in[i];
    v.x=rnd(v.x); v.y=rnd(v.y); v.z=rnd(v.z); v.w=rnd(v.w);
    *(float4*)&out[i] = v;
}
__global__ void prep_wcat(const float* __restrict__ wq_a_w, const float* __restrict__ wq_a_b,
                          const float* __restrict__ wkv_a_w, const float* __restrict__ wkv_a_b,
                          float* __restrict__ wcat, float* __restrict__ bcat){
    int n = blockIdx.x;
    const float* src = (n < 256) ? (wq_a_w + (size_t)n*DIM) : (wkv_a_w + (size_t)(n-256)*DIM);
    for (int k = threadIdx.x; k < DIM; k += 256) wcat[(size_t)n*DIM + k] = rnd(src[k]);
    if (threadIdx.x == 0) bcat[n] = (n < 256) ? wq_a_b[n] : wkv_a_b[n-256];
}
__global__ void prep_wc_kernel(const float* __restrict__ wq_b_w,
                               const float* __restrict__ wq_b_b,
                               const float* __restrict__ wkv_b_w,
                               float* __restrict__ wc, float* __restrict__ biasc) {
    int hc = blockIdx.x, h = hc >> 7, c = hc & 127, l = threadIdx.x;
    float acc = 0.f, accb = 0.f;
    #pragma unroll
    for (int q = 0; q < NDQK; q++) {
        float kb = wkv_b_w[(size_t)(h*(NDQK+NDV) + q)*DLKV + c];
        acc  = fmaf(kb, wq_b_w[(size_t)(h*NDQK + q)*DLQ + l], acc);
        accb = fmaf(kb, wq_b_b[h*NDQK + q], accb);
    }
    wc[(size_t)hc*DLQ + l] = rnd(acc);
    if (l == 0) biasc[hc] = accb;
}
// wo2[d][h*128+c] = sum_v wo_w[d, h*64+v] * wkv_b[h, 20+v, c]; smem-cached slices
__global__ __launch_bounds__(128) void prep_wo2_kernel(
    const float* __restrict__ wo_w, const float* __restrict__ wkv_b_w,
    float* __restrict__ wo2) {
    __shared__ float sv[64*128];
    __shared__ float sw[32*64];
    const int h = blockIdx.x, d0 = blockIdx.y*32, c = threadIdx.x;
    for (int i = threadIdx.x; i < 64*128; i += 128)
        sv[i] = wkv_b_w[(size_t)(h*(NDQK+NDV) + NDQK)*DLKV + i];
    for (int i = threadIdx.x; i < 32*64; i += 128)
        sw[i] = wo_w[(size_t)(d0 + (i>>6))*(NH*NDV) + h*NDV + (i&63)];
    __syncthreads();
    #pragma unroll 4
    for (int dd = 0; dd < 32; dd++){
        float acc = 0.f;
        #pragma unroll 8
        for (int v = 0; v < 64; v++) acc = fmaf(sw[dd*64 + v], sv[v*128 + c], acc);
        wo2[(size_t)(d0+dd)*(NH*DLKV) + h*DLKV + c] = rnd(acc);
    }
}

// ---------- RMSNorm ----------
__global__ void rms_kernel(const float* __restrict__ in, int ld, int off,
                           const float* __restrict__ w, float* __restrict__ out, int N) {
    int row = blockIdx.x;
    const float* x = in + (size_t)row*ld + off;
    float ss = 0.f;
    for (int i = threadIdx.x; i < N; i += 128) { float v = x[i]; ss = fmaf(v, v, ss); }
    #pragma unroll
    for (int d = 16; d; d >>= 1) ss += __shfl_xor_sync(0xffffffffu, ss, d);
    __shared__ float red[4];
    if ((threadIdx.x & 31) == 0) red[threadIdx.x >> 5] = ss;
    __syncthreads();
    float r = rsqrtf((red[0]+red[1]+red[2]+red[3]) / (float)N + 1e-6f);
    for (int i = threadIdx.x; i < N; i += 128)
        out[(size_t)row*N + i] = rnd(x[i] * r * w[i]);
}

// ---------- tf32 mma GEMM, cp.async 3-stage, ldmatrix, 1 sync/chunk ----------
template<bool ROUND>
__global__ __launch_bounds__(256, 2) void tgemm3(
    const float* __restrict__ A, const float* __restrict__ Bm,
    const float* __restrict__ bias, float* __restrict__ C,
    int M, int N, int K)
{
    extern __shared__ float smem[];
    const int SSZ = 2*128*36;          // floats per stage (A then B)

    const int mt = blockIdx.y*128, nt = blockIdx.x*128;
    const int tid = threadIdx.x, w = tid>>5, lane = tid&31;
    const int g = lane>>2, t = lane&3;
    const int wm = (w&3)*32, wn = (w>>2)*64;
    const int mat = lane>>3, r8 = lane&7;
    const int matr = mat&1, matc = mat>>1;

    const uint32_t smu = smem_u32(smem);
    const uint32_t aoff0 = (uint32_t)(((wm + matr*8 + r8)*36 + matc*4)*4);
    const uint32_t boff0 = (uint32_t)((128*36 + (wn + matc*8 + r8)*36 + matr*4)*4);

    float acc[2][8][4];
    #pragma unroll
    for (int i=0;i<2;i++)
        #pragma unroll
        for (int j=0;j<8;j++){ acc[i][j][0]=0.f; acc[i][j][1]=0.f; acc[i][j][2]=0.f; acc[i][j][3]=0.f; }

    const int NC = K >> 5;
    auto fetch = [&](int i, int slot){
        const int k0 = i << 5;
        float* dA = smem + slot*SSZ;
        float* dB = dA + 128*36;
        #pragma unroll
        for (int s2=0;s2<4;s2++){
            int v = tid + s2*256, r = v>>3, c4 = (v&7)<<2;
            cp16(smem_u32(&dA[r*36 + c4]), &A [(size_t)(mt+r)*K + k0 + c4]);
            cp16(smem_u32(&dB[r*36 + c4]), &Bm[(size_t)(nt+r)*K + k0 + c4]);
        }
        cp_commit();
    };
    fetch(0, 0);
    if (NC > 1) fetch(1, 1);

    for (int i=0;i<NC;i++){
        if (i == NC-1) cp_wait<0>(); else cp_wait<1>();
        __syncthreads();
        if (i+2 < NC) fetch(i+2, (i+2)%3);
        const uint32_t sb = smu + (uint32_t)((i%3)*SSZ*4);
        #pragma unroll
        for (int kk=0; kk<32; kk+=8){
            uint32_t af[2][4], bf[8][2];
            #pragma unroll
            for (int ii=0;ii<2;ii++)
                ldsm4(af[ii][0],af[ii][1],af[ii][2],af[ii][3],
                      sb + aoff0 + (uint32_t)(ii*16*36*4 + kk*4));
            #pragma unroll
            for (int p=0;p<4;p++){
                uint32_t r0,r1,r2,r3;
                ldsm4(r0,r1,r2,r3, sb + boff0 + (uint32_t)(p*16*36*4 + kk*4));
                bf[2*p][0]=r0; bf[2*p][1]=r1; bf[2*p+1][0]=r2; bf[2*p+1][1]=r3;
            }
            #pragma unroll
            for (int ii=0;ii<2;ii++)
                #pragma unroll
                for (int j=0;j<8;j++)
                    mma8(acc[ii][j][0],acc[ii][j][1],acc[ii][j][2],acc[ii][j][3],
                         af[ii][0],af[ii][1],af[ii][2],af[ii][3],bf[j][0],bf[j][1]);
        }
    }
    #pragma unroll
    for (int ii=0;ii<2;ii++){
        int row0 = mt + wm + ii*16 + g, row1 = row0 + 8;
        #pragma unroll
        for (int j=0;j<8;j++){
            int col = nt + wn + j*8 + 2*t;
            float b0v = bias[col], b1v = bias[col+1];
            float o00 = acc[ii][j][0]+b0v, o01 = acc[ii][j][1]+b1v;
            float o10 = acc[ii][j][2]+b0v, o11 = acc[ii][j][3]+b1v;
            if (ROUND){ o00=rnd(o00); o01=rnd(o01); o10=rnd(o10); o11=rnd(o11); }
            *(float2*)&C[(size_t)row0*N + col] = make_float2(o00, o01);
            *(float2*)&C[(size_t)row1*N + col] = make_float2(o10, o11);
        }
    }
}

// ---------- flash attention: ldsm S-frags, column-partitioned PV ----------
__global__ __launch_bounds__(128, 2) void attn_tc(
    const float* __restrict__ qkv, const float* __restrict__ kvn,
    float* __restrict__ vlat)
{
    extern __shared__ float smf[];
    float*    sKV = smf;                          // [2][64][132]
    uint32_t* sP  = (uint32_t*)(smf + 2*64*132);  // [64][68] tf32 bits
    float*    sAl = smf + 2*64*132 + 64*68;       // [64] alpha
    float*    sL  = sAl + 64;                     // [64] sum

    const int qt = (int)gridDim.x - 1 - (int)blockIdx.x;
    const int h = blockIdx.y, b = blockIdx.z;
    const int tid = threadIdx.x, w = tid>>5, lane = tid & 31;
    const int g = lane >> 2, t = lane & 3;
    const int mat = lane>>3, r8 = lane&7;
    const int matr = mat&1, matc = mat>>1;
    const int q0 = qt*64;
    const int mrow = w*16 + g;
    const int wn = w*32;
    const float scale = 0.22360679774997896f;

    const uint32_t kvu = smem_u32(sKV);
    const uint32_t pu  = smem_u32(sP);
    const uint32_t koff0 = (uint32_t)(((matc*8 + r8)*132 + matr*4)*4);
    const uint32_t poff0 = (uint32_t)(((matr*8 + r8)*68 + matc*4)*4);

    {
        #pragma unroll
        for (int s2=0;s2<16;s2++){
            int v = tid + s2*128, r = v>>5, c4 = (v&31)<<2;
            cp16(smem_u32(&sKV[r*132 + c4]), &kvn[((size_t)(b*SQ + r))*128 + c4]);
        }
        cp_commit();
    }
    uint32_t qf[16][4];
    {
        const float* qb = &qkv[((size_t)((b*SQ + q0)*NH + h))*128];
        const size_t rs = (size_t)NH*128;
        #pragma unroll
        for (int kk = 0; kk < 16; kk++) {
            qf[kk][0] = ldb(qb + (size_t)(mrow  )*rs + kk*8 + t);
            qf[kk][1] = ldb(qb + (size_t)(mrow+8)*rs + kk*8 + t);
            qf[kk][2] = ldb(qb + (size_t)(mrow  )*rs + kk*8 + t + 4);
            qf[kk][3] = ldb(qb + (size_t)(mrow+8)*rs + kk*8 + t + 4);
        }
    }

    float o[4][4][4];
    #pragma unroll
    for (int mi=0;mi<4;mi++)
        #pragma unroll
        for (int j=0;j<4;j++){ o[mi][j][0]=0.f; o[mi][j][1]=0.f; o[mi][j][2]=0.f; o[mi][j][3]=0.f; }
    float m0=-1e30f, m1=-1e30f, l0=0.f, l1=0.f;

    for (int kt = 0; kt <= qt; kt++) {
        const int st = kt & 1;
        __syncthreads();
        if (kt < qt) {
            const int k0n = (kt+1)*64;
            float* dst = sKV + (1-st)*64*132;
            #pragma unroll
            for (int s2=0;s2<16;s2++){
                int v = tid + s2*128, r = v>>5, c4 = (v&31)<<2;
                cp16(smem_u32(&dst[r*132 + c4]), &kvn[((size_t)(b*SQ + k0n + r))*128 + c4]);
            }
            cp_commit();
            cp_wait<1>();
        } else {
            cp_wait<0>();
        }
        __syncthreads();
        const float* cKV = sKV + st*64*132;
        const uint32_t kB = kvu + (uint32_t)(st*64*132*4);
        const int k0 = kt*64;

        float s[8][4];
        #pragma unroll
        for (int j = 0; j < 8; j++) { s[j][0]=0.f; s[j][1]=0.f; s[j][2]=0.f; s[j][3]=0.f; }
        #pragma unroll
        for (int kk = 0; kk < 16; kk++) {
            uint32_t bf[8][2];
            #pragma unroll
            for (int p=0;p<4;p++){
                uint32_t r0,r1,r2,r3;
                ldsm4(r0,r1,r2,r3, kB + koff0 + (uint32_t)(p*16*132*4 + kk*8*4));
                bf[2*p][0]=r0; bf[2*p][1]=r1; bf[2*p+1][0]=r2; bf[2*p+1][1]=r3;
            }
            #pragma unroll
            for (int j = 0; j < 8; j++)
                mma8(s[j][0],s[j][1],s[j][2],s[j][3], qf[kk][0],qf[kk][1],qf[kk][2],qf[kk][3],
                     bf[j][0],bf[j][1]);
        }

        const bool diag = (kt == qt);
        const int grow0 = q0 + mrow, grow1 = grow0 + 8;
        float mx0=-1e30f, mx1=-1e30f;
        #pragma unroll
        for (int j = 0; j < 8; j++) {
            int c = k0 + j*8 + 2*t;
            #pragma unroll
            for (int e = 0; e < 2; e++) {
                float v0 = s[j][e]*scale, v1 = s[j][2+e]*scale;
                if (diag && (c+e) > grow0) v0 = -1e30f;
                if (diag && (c+e) > grow1) v1 = -1e30f;
                s[j][e] = v0; s[j][2+e] = v1;
                mx0 = fmaxf(mx0, v0); mx1 = fmaxf(mx1, v1);
            }
        }
        mx0 = fmaxf(mx0, __shfl_xor_sync(0xffffffffu, mx0, 1));
        mx0 = fmaxf(mx0, __shfl_xor_sync(0xffffffffu, mx0, 2));
        mx1 = fmaxf(mx1, __shfl_xor_sync(0xffffffffu, mx1, 1));
        mx1 = fmaxf(mx1, __shfl_xor_sync(0xffffffffu, mx1, 2));
        float nm0 = fmaxf(m0, mx0), nm1 = fmaxf(m1, mx1);
        float al0 = __expf(m0 - nm0), al1 = __expf(m1 - nm1);
        m0 = nm0; m1 = nm1;
        float ls0 = 0.f, ls1 = 0.f;
        #pragma unroll
        for (int j = 0; j < 8; j++) {
            float p00 = __expf(s[j][0]-nm0), p01 = __expf(s[j][1]-nm0);
            float p10 = __expf(s[j][2]-nm1), p11 = __expf(s[j][3]-nm1);
            ls0 += p00 + p01; ls1 += p10 + p11;
            int c = j*8 + 2*t;
            sP[(mrow  )*68 + c] = f2tf(p00); sP[(mrow  )*68 + c+1] = f2tf(p01);
            sP[(mrow+8)*68 + c] = f2tf(p10); sP[(mrow+8)*68 + c+1] = f2tf(p11);
        }
        ls0 += __shfl_xor_sync(0xffffffffu, ls0, 1);
        ls0 += __shfl_xor_sync(0xffffffffu, ls0, 2);
        ls1 += __shfl_xor_sync(0xffffffffu, ls1, 1);
        ls1 += __shfl_xor_sync(0xffffffffu, ls1, 2);
        l0 = l0*al0 + ls0; l1 = l1*al1 + ls1;
        if (t == 0){ sAl[mrow] = al0; sAl[mrow+8] = al1; }
        __syncthreads();

        float alo[4], ahi[4];
        #pragma unroll
        for (int mi=0;mi<4;mi++){ alo[mi]=sAl[mi*16+g]; ahi[mi]=sAl[mi*16+8+g]; }
        #pragma unroll
        for (int mi=0;mi<4;mi++)
            #pragma unroll
            for (int j=0;j<4;j++){
                o[mi][j][0]*=alo[mi]; o[mi][j][1]*=alo[mi];
                o[mi][j][2]*=ahi[mi]; o[mi][j][3]*=ahi[mi];
            }
        #pragma unroll
        for (int kb = 0; kb < 64; kb += 8) {
            uint32_t pf[4][4];
            #pragma unroll
            for (int mi=0;mi<4;mi++)
                ldsm4(pf[mi][0],pf[mi][1],pf[mi][2],pf[mi][3],
                      pu + poff0 + (uint32_t)(mi*16*68*4 + kb*4));
            #pragma unroll
            for (int j=0;j<4;j++){
                uint32_t b0 = ldb(&cKV[(kb+t  )*132 + wn + j*8 + g]);
                uint32_t b1 = ldb(&cKV[(kb+t+4)*132 + wn + j*8 + g]);
                #pragma unroll
                for (int mi=0;mi<4;mi++)
                    mma8(o[mi][j][0],o[mi][j][1],o[mi][j][2],o[mi][j][3],
                         pf[mi][0],pf[mi][1],pf[mi][2],pf[mi][3], b0,b1);
            }
        }
    }

    if (t == 0){ sL[mrow] = l0; sL[mrow+8] = l1; }
    __syncthreads();
    #pragma unroll
    for (int mi=0;mi<4;mi++){
        int lr0 = mi*16 + g, lr1 = lr0 + 8;
        float inv0 = 1.f/sL[lr0], inv1 = 1.f/sL[lr1];
        size_t base0 = ((size_t)((b*SQ + q0 + lr0)*NH + h))*128 + wn;
        size_t base1 = ((size_t)((b*SQ + q0 + lr1)*NH + h))*128 + wn;
        #pragma unroll
        for (int j=0;j<4;j++){
            int col = j*8 + 2*t;
            *(float2*)&vlat[base0 + col] = make_float2(rnd(o[mi][j][0]*inv0), rnd(o[mi][j][1]*inv0));
            *(float2*)&vlat[base1 + col] = make_float2(rnd(o[mi][j][2]*inv1), rnd(o[mi][j][3]*inv1));
        }
    }
}

// ---------- launch ----------
extern "C" void kernel_launch(void* const* d_in, const int* in_sizes, int n_in,
                              void* d_out, int out_size)
{
    const float* h_ptr     = (const float*)d_in[0];
    const float* wq_a_w    = (const float*)d_in[2];
    const float* wq_a_b    = (const float*)d_in[3];
    const float* q_norm_w  = (const float*)d_in[4];
    const float* wq_b_w    = (const float*)d_in[5];
    const float* wq_b_b    = (const float*)d_in[6];
    const float* wkv_a_w   = (const float*)d_in[7];
    const float* wkv_a_b   = (const float*)d_in[8];
    const float* kv_norm_w = (const float*)d_in[9];
    const float* wkv_b_w   = (const float*)d_in[10];
    const float* wo_w      = (const float*)d_in[11];
    const float* wo_b      = (const float*)d_in[12];
    float* out = (float*)d_out;

    float *hrnd, *projcat, *qlat, *kvn, *qkv, *vlat, *wc, *biasc, *wo2, *wcat, *bcat;
    cudaGetSymbolAddress((void**)&hrnd,  g_hrnd);
    cudaGetSymbolAddress((void**)&projcat, g_projcat);
    cudaGetSymbolAddress((void**)&qlat,  g_qlat);
    cudaGetSymbolAddress((void**)&kvn,   g_kvn);
    cudaGetSymbolAddress((void**)&qkv,   g_qkv);
    cudaGetSymbolAddress((void**)&vlat,  g_vlat);
    cudaGetSymbolAddress((void**)&wc,    g_wc);
    cudaGetSymbolAddress((void**)&biasc, g_biasc);
    cudaGetSymbolAddress((void**)&wo2,   g_wo2);
    cudaGetSymbolAddress((void**)&wcat,  g_wcat);
    cudaGetSymbolAddress((void**)&bcat,  g_bcat);

    const int gsm  = 3*2*128*36*4;                       // 110592
    const int asm_ = (2*64*132 + 64*68 + 128)*4;         // 85504
    cudaFuncSetAttribute((tgemm3<true>),  cudaFuncAttributeMaxDynamicSharedMemorySize, gsm);
    cudaFuncSetAttribute((tgemm3<false>), cudaFuncAttributeMaxDynamicSharedMemorySize, gsm);
    cudaFuncSetAttribute(attn_tc, cudaFuncAttributeMaxDynamicSharedMemorySize, asm_);

    round_copy<<<NTOK*DIM/1024, 256>>>(h_ptr, hrnd);
    prep_wcat<<<384, 256>>>(wq_a_w, wq_a_b, wkv_a_w, wkv_a_b, wcat, bcat);
    prep_wc_kernel<<<NH*DLKV, DLQ>>>(wq_b_w, wq_b_b, wkv_b_w, wc, biasc);
    prep_wo2_kernel<<<dim3(NH, 32), 128>>>(wo_w, wkv_b_w, wo2);

    // merged latent projections: [8192,1024] x [384,1024]^T
    tgemm3<false><<<dim3(3, NTOK/128), 256, gsm>>>(hrnd, wcat, bcat, projcat, NTOK, 384, DIM);
    rms_kernel<<<NTOK, 128>>>(projcat, 384, 0,   q_norm_w,  qlat, DLQ);
    rms_kernel<<<NTOK, 128>>>(projcat, 384, 256, kv_norm_w, kvn,  DLKV);

    // absorbed q -> latent-kv: [8192,256] x [2048,256]^T (rounded for attention)
    tgemm3<true><<<dim3(16, NTOK/128), 256, gsm>>>(qlat, wc, biasc, qkv, NTOK, NH*DLKV, DLQ);

    attn_tc<<<dim3(SQ/64, NH, BB), 128, asm_>>>(qkv, kvn, vlat);

    // absorbed v -> out: [8192,2048] x [1024,2048]^T
    tgemm3<false><<<dim3(8, NTOK/128), 256, gsm>>>(vlat, wo2, wo_b, out, NTOK, DIM, NH*DLKV);
}

// round 9
// speedup vs baseline: 5.1025x; 1.1466x over previous
#include <cuda_runtime.h>
#include <cstdint>

#define SQ   2048
#define BB   4
#define DIM  1024
#define NH   16
#define NDQK 20
#define NDV  64
#define DLQ  256
#define DLKV 128
#define NTOK (BB*SQ)

__device__ float g_hrnd[(size_t)NTOK*DIM];
__device__ float g_projcat[(size_t)NTOK*384];
__device__ float g_qlat[NTOK*DLQ];
__device__ float g_kvn [NTOK*DLKV];
__device__ float g_qkv [(size_t)NTOK*NH*DLKV];
__device__ float g_vlat[(size_t)NTOK*NH*DLKV];
__device__ float g_v   [(size_t)NTOK*NH*NDV];
__device__ float g_wc  [NH*DLKV*DLQ];
__device__ float g_biasc[NH*DLKV];
__device__ float g_worn[DIM*NH*NDV];
__device__ float g_wkvbv[NH*NDV*DLKV];
__device__ float g_wcat[384*DIM];
__device__ float g_bcat[384];

// ======================= helpers =======================
__device__ __forceinline__ uint32_t f2tf(float f){
    uint32_t u; asm("cvt.rna.tf32.f32 %0, %1;" : "=r"(u) : "f"(f)); return u;
}
__device__ __forceinline__ float rnd(float f){ return __uint_as_float(f2tf(f)); }
__device__ __forceinline__ void mma8(float&c0,float&c1,float&c2,float&c3,
    uint32_t a0,uint32_t a1,uint32_t a2,uint32_t a3,uint32_t b0,uint32_t b1){
    asm volatile("mma.sync.aligned.m16n8k8.row.col.f32.tf32.tf32.f32 "
        "{%0,%1,%2,%3}, {%4,%5,%6,%7}, {%8,%9}, {%0,%1,%2,%3};"
        : "+f"(c0),"+f"(c1),"+f"(c2),"+f"(c3)
        : "r"(a0),"r"(a1),"r"(a2),"r"(a3),"r"(b0),"r"(b1));
}
__device__ __forceinline__ void ldsm4(uint32_t&r0,uint32_t&r1,uint32_t&r2,uint32_t&r3,uint32_t a){
    asm volatile("ldmatrix.sync.aligned.m8n8.x4.shared.b16 {%0,%1,%2,%3}, [%4];"
        : "=r"(r0),"=r"(r1),"=r"(r2),"=r"(r3) : "r"(a));
}
__device__ __forceinline__ uint32_t smem_u32(const void* p){
    uint32_t a;
    asm("{ .reg .u64 t; cvta.to.shared.u64 t, %1; cvt.u32.u64 %0, t; }" : "=r"(a) : "l"(p));
    return a;
}
__device__ __forceinline__ void cp16(uint32_t dst, const void* src){
    asm volatile("cp.async.cg.shared.global [%0], [%1], 16;" :: "r"(dst), "l"(src));
}
__device__ __forceinline__ void cp_commit(){ asm volatile("cp.async.commit_group;" ::: "memory"); }
template<int NW> __device__ __forceinline__ void cp_wait(){
    asm volatile("cp.async.wait_group %0;" :: "n"(NW) : "memory");
}
__device__ __forceinline__ uint32_t ldb(const float* p){ return __float_as_uint(*p); }

// ---------- prep ----------
__global__ void round_copy(const float* __restrict__ in, float* __restrict__ out){
    size_t i = ((size_t)blockIdx.x*256 + threadIdx.x)*4;
    float4 v = *(const float4*)&in[i];
    v.x=rnd(v.x); v.y=rnd(v.y); v.z=rnd(v.z); v.w=rnd(v.w);
    *(float4*)&out[i] = v;
}
__global__ void prep_wkvbv(const float* __restrict__ wkv_b_w, float* __restrict__ outp){
    int i = blockIdx.x*256 + threadIdx.x;          // over NH*64*128
    int h = i >> 13, rem = i & 8191;
    outp[i] = rnd(wkv_b_w[(size_t)(h*(NDQK+NDV) + NDQK)*DLKV + rem]);
}
__global__ void prep_wcat(const float* __restrict__ wq_a_w, const float* __restrict__ wq_a_b,
                          const float* __restrict__ wkv_a_w, const float* __restrict__ wkv_a_b,
                          float* __restrict__ wcat, float* __restrict__ bcat){
    int n = blockIdx.x;
    const float* src = (n < 256) ? (wq_a_w + (size_t)n*DIM) : (wkv_a_w + (size_t)(n-256)*DIM);
    for (int k = threadIdx.x; k < DIM; k += 256) wcat[(size_t)n*DIM + k] = rnd(src[k]);
    if (threadIdx.x == 0) bcat[n] = (n < 256) ? wq_a_b[n] : wkv_a_b[n-256];
}
__global__ void prep_wc_kernel(const float* __restrict__ wq_b_w,
                               const float* __restrict__ wq_b_b,
                               const float* __restrict__ wkv_b_w,
                               float* __restrict__ wc, float* __restrict__ biasc) {
    int hc = blockIdx.x, h = hc >> 7, c = hc & 127, l = threadIdx.x;
    float acc = 0.f, accb = 0.f;
    #pragma unroll
    for (int q = 0; q < NDQK; q++) {
        float kb = wkv_b_w[(size_t)(h*(NDQK+NDV) + q)*DLKV + c];
        acc  = fmaf(kb, wq_b_w[(size_t)(h*NDQK + q)*DLQ + l], acc);
        accb = fmaf(kb, wq_b_b[h*NDQK + q], accb);
    }
    wc[(size_t)hc*DLQ + l] = rnd(acc);
    if (l == 0) biasc[hc] = accb;
}

// ---------- RMSNorm ----------
__global__ void rms_kernel(const float* __restrict__ in, int ld, int off,
                           const float* __restrict__ w, float* __restrict__ out, int N) {
    int row = blockIdx.x;
    const float* x = in + (size_t)row*ld + off;
    float ss = 0.f;
    for (int i = threadIdx.x; i < N; i += 128) { float v = x[i]; ss = fmaf(v, v, ss); }
    #pragma unroll
    for (int d = 16; d; d >>= 1) ss += __shfl_xor_sync(0xffffffffu, ss, d);
    __shared__ float red[4];
    if ((threadIdx.x & 31) == 0) red[threadIdx.x >> 5] = ss;
    __syncthreads();
    float r = rsqrtf((red[0]+red[1]+red[2]+red[3]) / (float)N + 1e-6f);
    for (int i = threadIdx.x; i < N; i += 128)
        out[(size_t)row*N + i] = rnd(x[i] * r * w[i]);
}

// ---------- tf32 mma GEMM, cp.async 3-stage, ldmatrix, z-batched ----------
// C[m, nt+n] (+= bias) = sum_k A[m,k] * B[n,k]; per-z pointer strides.
template<int BN, bool ROUND, bool BIAS>
__global__ __launch_bounds__(256, 2) void tgemm3(
    const float* __restrict__ A, int lda, size_t sAz,
    const float* __restrict__ Bm, int ldb, size_t sBz,
    const float* __restrict__ bias, float* __restrict__ C, int ldc, size_t sCz,
    int K)
{
    extern __shared__ float smem[];
    const int SSZ = (128+BN)*36;       // floats per stage (A then B)
    constexpr int NJ = BN/16;          // 8-col groups per warp
    constexpr int NP = BN/32;          // ldsm x4 B loads per kk

    const int mt = blockIdx.y*128, nt = blockIdx.x*BN;
    A  += (size_t)blockIdx.z*sAz;
    Bm += (size_t)blockIdx.z*sBz;
    C  += (size_t)blockIdx.z*sCz;

    const int tid = threadIdx.x, w = tid>>5, lane = tid&31;
    const int g = lane>>2, t = lane&3;
    const int wm = (w&3)*32, wn = (w>>2)*(BN/2);
    const int mat = lane>>3, r8 = lane&7;
    const int matr = mat&1, matc = mat>>1;

    const uint32_t smu = smem_u32(smem);
    const uint32_t aoff0 = (uint32_t)(((wm + matr*8 + r8)*36 + matc*4)*4);
    const uint32_t boff0 = (uint32_t)((128*36 + (wn + matc*8 + r8)*36 + matr*4)*4);

    float acc[2][NJ][4];
    #pragma unroll
    for (int i=0;i<2;i++)
        #pragma unroll
        for (int j=0;j<NJ;j++){ acc[i][j][0]=0.f; acc[i][j][1]=0.f; acc[i][j][2]=0.f; acc[i][j][3]=0.f; }

    const int NC = K >> 5;
    auto fetch = [&](int i, int slot){
        const int k0 = i << 5;
        float* dA = smem + slot*SSZ;
        float* dB = dA + 128*36;
        #pragma unroll
        for (int s2=0;s2<4;s2++){
            int v = tid + s2*256, r = v>>3, c4 = (v&7)<<2;
            cp16(smem_u32(&dA[r*36 + c4]), &A[(size_t)(mt+r)*lda + k0 + c4]);
        }
        #pragma unroll
        for (int s2=0;s2<BN/32;s2++){
            int v = tid + s2*256, r = v>>3, c4 = (v&7)<<2;
            cp16(smem_u32(&dB[r*36 + c4]), &Bm[(size_t)(nt+r)*ldb + k0 + c4]);
        }
        cp_commit();
    };
    fetch(0, 0);
    if (NC > 1) fetch(1, 1);

    for (int i=0;i<NC;i++){
        if (i == NC-1) cp_wait<0>(); else cp_wait<1>();
        __syncthreads();
        if (i+2 < NC) fetch(i+2, (i+2)%3);
        const uint32_t sb = smu + (uint32_t)((i%3)*SSZ*4);
        #pragma unroll
        for (int kk=0; kk<32; kk+=8){
            uint32_t af[2][4], bf[NJ][2];
            #pragma unroll
            for (int ii=0;ii<2;ii++)
                ldsm4(af[ii][0],af[ii][1],af[ii][2],af[ii][3],
                      sb + aoff0 + (uint32_t)(ii*16*36*4 + kk*4));
            #pragma unroll
            for (int p=0;p<NP;p++){
                uint32_t r0,r1,r2,r3;
                ldsm4(r0,r1,r2,r3, sb + boff0 + (uint32_t)(p*16*36*4 + kk*4));
                bf[2*p][0]=r0; bf[2*p][1]=r1; bf[2*p+1][0]=r2; bf[2*p+1][1]=r3;
            }
            #pragma unroll
            for (int ii=0;ii<2;ii++)
                #pragma unroll
                for (int j=0;j<NJ;j++)
                    mma8(acc[ii][j][0],acc[ii][j][1],acc[ii][j][2],acc[ii][j][3],
                         af[ii][0],af[ii][1],af[ii][2],af[ii][3],bf[j][0],bf[j][1]);
        }
    }
    #pragma unroll
    for (int ii=0;ii<2;ii++){
        int row0 = mt + wm + ii*16 + g, row1 = row0 + 8;
        #pragma unroll
        for (int j=0;j<NJ;j++){
            int col = nt + wn + j*8 + 2*t;
            float b0v = BIAS ? bias[col] : 0.f, b1v = BIAS ? bias[col+1] : 0.f;
            float o00 = acc[ii][j][0]+b0v, o01 = acc[ii][j][1]+b1v;
            float o10 = acc[ii][j][2]+b0v, o11 = acc[ii][j][3]+b1v;
            if (ROUND){ o00=rnd(o00); o01=rnd(o01); o10=rnd(o10); o11=rnd(o11); }
            *(float2*)&C[(size_t)row0*ldc + col] = make_float2(o00, o01);
            *(float2*)&C[(size_t)row1*ldc + col] = make_float2(o10, o11);
        }
    }
}

// ---------- flash attention: ldsm S-frags, column-partitioned PV ----------
__global__ __launch_bounds__(128, 2) void attn_tc(
    const float* __restrict__ qkv, const float* __restrict__ kvn,
    float* __restrict__ vlat)
{
    extern __shared__ float smf[];
    float*    sKV = smf;                          // [2][64][132]
    uint32_t* sP  = (uint32_t*)(smf + 2*64*132);  // [64][68] tf32 bits
    float*    sAl = smf + 2*64*132 + 64*68;       // [64] alpha
    float*    sL  = sAl + 64;                     // [64] sum

    const int qt = (int)gridDim.x - 1 - (int)blockIdx.x;
    const int h = blockIdx.y, b = blockIdx.z;
    const int tid = threadIdx.x, w = tid>>5, lane = tid & 31;
    const int g = lane >> 2, t = lane & 3;
    const int mat = lane>>3, r8 = lane&7;
    const int matr = mat&1, matc = mat>>1;
    const int q0 = qt*64;
    const int mrow = w*16 + g;
    const int wn = w*32;
    const float scale = 0.22360679774997896f;

    const uint32_t kvu = smem_u32(sKV);
    const uint32_t pu  = smem_u32(sP);
    const uint32_t koff0 = (uint32_t)(((matc*8 + r8)*132 + matr*4)*4);
    const uint32_t poff0 = (uint32_t)(((matr*8 + r8)*68 + matc*4)*4);

    {
        #pragma unroll
        for (int s2=0;s2<16;s2++){
            int v = tid + s2*128, r = v>>5, c4 = (v&31)<<2;
            cp16(smem_u32(&sKV[r*132 + c4]), &kvn[((size_t)(b*SQ + r))*128 + c4]);
        }
        cp_commit();
    }
    uint32_t qf[16][4];
    {
        const float* qb = &qkv[((size_t)((b*SQ + q0)*NH + h))*128];
        const size_t rs = (size_t)NH*128;
        #pragma unroll
        for (int kk = 0; kk < 16; kk++) {
            qf[kk][0] = ldb(qb + (size_t)(mrow  )*rs + kk*8 + t);
            qf[kk][1] = ldb(qb + (size_t)(mrow+8)*rs + kk*8 + t);
            qf[kk][2] = ldb(qb + (size_t)(mrow  )*rs + kk*8 + t + 4);
            qf[kk][3] = ldb(qb + (size_t)(mrow+8)*rs + kk*8 + t + 4);
        }
    }

    float o[4][4][4];
    #pragma unroll
    for (int mi=0;mi<4;mi++)
        #pragma unroll
        for (int j=0;j<4;j++){ o[mi][j][0]=0.f; o[mi][j][1]=0.f; o[mi][j][2]=0.f; o[mi][j][3]=0.f; }
    float m0=-1e30f, m1=-1e30f, l0=0.f, l1=0.f;

    for (int kt = 0; kt <= qt; kt++) {
        const int st = kt & 1;
        __syncthreads();
        if (kt < qt) {
            const int k0n = (kt+1)*64;
            float* dst = sKV + (1-st)*64*132;
            #pragma unroll
            for (int s2=0;s2<16;s2++){
                int v = tid + s2*128, r = v>>5, c4 = (v&31)<<2;
                cp16(smem_u32(&dst[r*132 + c4]), &kvn[((size_t)(b*SQ + k0n + r))*128 + c4]);
            }
            cp_commit();
            cp_wait<1>();
        } else {
            cp_wait<0>();
        }
        __syncthreads();
        const float* cKV = sKV + st*64*132;
        const uint32_t kB = kvu + (uint32_t)(st*64*132*4);
        const int k0 = kt*64;

        float s[8][4];
        #pragma unroll
        for (int j = 0; j < 8; j++) { s[j][0]=0.f; s[j][1]=0.f; s[j][2]=0.f; s[j][3]=0.f; }
        #pragma unroll
        for (int kk = 0; kk < 16; kk++) {
            uint32_t bf[8][2];
            #pragma unroll
            for (int p=0;p<4;p++){
                uint32_t r0,r1,r2,r3;
                ldsm4(r0,r1,r2,r3, kB + koff0 + (uint32_t)(p*16*132*4 + kk*8*4));
                bf[2*p][0]=r0; bf[2*p][1]=r1; bf[2*p+1][0]=r2; bf[2*p+1][1]=r3;
            }
            #pragma unroll
            for (int j = 0; j < 8; j++)
                mma8(s[j][0],s[j][1],s[j][2],s[j][3], qf[kk][0],qf[kk][1],qf[kk][2],qf[kk][3],
                     bf[j][0],bf[j][1]);
        }

        const bool diag = (kt == qt);
        const int grow0 = q0 + mrow, grow1 = grow0 + 8;
        float mx0=-1e30f, mx1=-1e30f;
        #pragma unroll
        for (int j = 0; j < 8; j++) {
            int c = k0 + j*8 + 2*t;
            #pragma unroll
            for (int e = 0; e < 2; e++) {
                float v0 = s[j][e]*scale, v1 = s[j][2+e]*scale;
                if (diag && (c+e) > grow0) v0 = -1e30f;
                if (diag && (c+e) > grow1) v1 = -1e30f;
                s[j][e] = v0; s[j][2+e] = v1;
                mx0 = fmaxf(mx0, v0); mx1 = fmaxf(mx1, v1);
            }
        }
        mx0 = fmaxf(mx0, __shfl_xor_sync(0xffffffffu, mx0, 1));
        mx0 = fmaxf(mx0, __shfl_xor_sync(0xffffffffu, mx0, 2));
        mx1 = fmaxf(mx1, __shfl_xor_sync(0xffffffffu, mx1, 1));
        mx1 = fmaxf(mx1, __shfl_xor_sync(0xffffffffu, mx1, 2));
        float nm0 = fmaxf(m0, mx0), nm1 = fmaxf(m1, mx1);
        float al0 = __expf(m0 - nm0), al1 = __expf(m1 - nm1);
        m0 = nm0; m1 = nm1;
        float ls0 = 0.f, ls1 = 0.f;
        #pragma unroll
        for (int j = 0; j < 8; j++) {
            float p00 = __expf(s[j][0]-nm0), p01 = __expf(s[j][1]-nm0);
            float p10 = __expf(s[j][2]-nm1), p11 = __expf(s[j][3]-nm1);
            ls0 += p00 + p01; ls1 += p10 + p11;
            int c = j*8 + 2*t;
            sP[(mrow  )*68 + c] = f2tf(p00); sP[(mrow  )*68 + c+1] = f2tf(p01);
            sP[(mrow+8)*68 + c] = f2tf(p10); sP[(mrow+8)*68 + c+1] = f2tf(p11);
        }
        ls0 += __shfl_xor_sync(0xffffffffu, ls0, 1);
        ls0 += __shfl_xor_sync(0xffffffffu, ls0, 2);
        ls1 += __shfl_xor_sync(0xffffffffu, ls1, 1);
        ls1 += __shfl_xor_sync(0xffffffffu, ls1, 2);
        l0 = l0*al0 + ls0; l1 = l1*al1 + ls1;
        if (t == 0){ sAl[mrow] = al0; sAl[mrow+8] = al1; }
        __syncthreads();

        float alo[4], ahi[4];
        #pragma unroll
        for (int mi=0;mi<4;mi++){ alo[mi]=sAl[mi*16+g]; ahi[mi]=sAl[mi*16+8+g]; }
        #pragma unroll
        for (int mi=0;mi<4;mi++)
            #pragma unroll
            for (int j=0;j<4;j++){
                o[mi][j][0]*=alo[mi]; o[mi][j][1]*=alo[mi];
                o[mi][j][2]*=ahi[mi]; o[mi][j][3]*=ahi[mi];
            }
        #pragma unroll
        for (int kb = 0; kb < 64; kb += 8) {
            uint32_t pf[4][4];
            #pragma unroll
            for (int mi=0;mi<4;mi++)
                ldsm4(pf[mi][0],pf[mi][1],pf[mi][2],pf[mi][3],
                      pu + poff0 + (uint32_t)(mi*16*68*4 + kb*4));
            #pragma unroll
            for (int j=0;j<4;j++){
                uint32_t b0 = ldb(&cKV[(kb+t  )*132 + wn + j*8 + g]);
                uint32_t b1 = ldb(&cKV[(kb+t+4)*132 + wn + j*8 + g]);
                #pragma unroll
                for (int mi=0;mi<4;mi++)
                    mma8(o[mi][j][0],o[mi][j][1],o[mi][j][2],o[mi][j][3],
                         pf[mi][0],pf[mi][1],pf[mi][2],pf[mi][3], b0,b1);
            }
        }
    }

    if (t == 0){ sL[mrow] = l0; sL[mrow+8] = l1; }
    __syncthreads();
    #pragma unroll
    for (int mi=0;mi<4;mi++){
        int lr0 = mi*16 + g, lr1 = lr0 + 8;
        float inv0 = 1.f/sL[lr0], inv1 = 1.f/sL[lr1];
        size_t base0 = ((size_t)((b*SQ + q0 + lr0)*NH + h))*128 + wn;
        size_t base1 = ((size_t)((b*SQ + q0 + lr1)*NH + h))*128 + wn;
        #pragma unroll
        for (int j=0;j<4;j++){
            int col = j*8 + 2*t;
            *(float2*)&vlat[base0 + col] = make_float2(rnd(o[mi][j][0]*inv0), rnd(o[mi][j][1]*inv0));
            *(float2*)&vlat[base1 + col] = make_float2(rnd(o[mi][j][2]*inv1), rnd(o[mi][j][3]*inv1));
        }
    }
}

// ---------- launch ----------
extern "C" void kernel_launch(void* const* d_in, const int* in_sizes, int n_in,
                              void* d_out, int out_size)
{
    const float* h_ptr     = (const float*)d_in[0];
    const float* wq_a_w    = (const float*)d_in[2];
    const float* wq_a_b    = (const float*)d_in[3];
    const float* q_norm_w  = (const float*)d_in[4];
    const float* wq_b_w    = (const float*)d_in[5];
    const float* wq_b_b    = (const float*)d_in[6];
    const float* wkv_a_w   = (const float*)d_in[7];
    const float* wkv_a_b   = (const float*)d_in[8];
    const float* kv_norm_w = (const float*)d_in[9];
    const float* wkv_b_w   = (const float*)d_in[10];
    const float* wo_w      = (const float*)d_in[11];
    const float* wo_b      = (const float*)d_in[12];
    float* out = (float*)d_out;

    float *hrnd, *projcat, *qlat, *kvn, *qkv, *vlat, *vv, *wc, *biasc, *worn, *wkvbv, *wcat, *bcat;
    cudaGetSymbolAddress((void**)&hrnd,  g_hrnd);
    cudaGetSymbolAddress((void**)&projcat, g_projcat);
    cudaGetSymbolAddress((void**)&qlat,  g_qlat);
    cudaGetSymbolAddress((void**)&kvn,   g_kvn);
    cudaGetSymbolAddress((void**)&qkv,   g_qkv);
    cudaGetSymbolAddress((void**)&vlat,  g_vlat);
    cudaGetSymbolAddress((void**)&vv,    g_v);
    cudaGetSymbolAddress((void**)&wc,    g_wc);
    cudaGetSymbolAddress((void**)&biasc, g_biasc);
    cudaGetSymbolAddress((void**)&worn,  g_worn);
    cudaGetSymbolAddress((void**)&wkvbv, g_wkvbv);
    cudaGetSymbolAddress((void**)&wcat,  g_wcat);
    cudaGetSymbolAddress((void**)&bcat,  g_bcat);

    const int gsm128 = 3*(128+128)*36*4;                 // 110592
    const int gsm64  = 3*(128+64)*36*4;                  // 82944
    const int asm_   = (2*64*132 + 64*68 + 128)*4;       // 85504
    cudaFuncSetAttribute((tgemm3<128,true,true>),   cudaFuncAttributeMaxDynamicSharedMemorySize, gsm128);
    cudaFuncSetAttribute((tgemm3<128,false,true>),  cudaFuncAttributeMaxDynamicSharedMemorySize, gsm128);
    cudaFuncSetAttribute((tgemm3<64,true,false>),   cudaFuncAttributeMaxDynamicSharedMemorySize, gsm64);
    cudaFuncSetAttribute(attn_tc, cudaFuncAttributeMaxDynamicSharedMemorySize, asm_);

    round_copy<<<NTOK*DIM/1024, 256>>>(h_ptr, hrnd);
    round_copy<<<DIM*NH*NDV/1024, 256>>>(wo_w, worn);
    prep_wkvbv<<<NH*NDV*DLKV/256, 256>>>(wkv_b_w, wkvbv);
    prep_wcat<<<384, 256>>>(wq_a_w, wq_a_b, wkv_a_w, wkv_a_b, wcat, bcat);
    prep_wc_kernel<<<NH*DLKV, DLQ>>>(wq_b_w, wq_b_b, wkv_b_w, wc, biasc);

    // merged latent projections: [8192,1024] x [384,1024]^T
    tgemm3<128,false,true><<<dim3(3, NTOK/128, 1), 256, gsm128>>>(
        hrnd, DIM, 0, wcat, DIM, 0, bcat, projcat, 384, 0, DIM);
    rms_kernel<<<NTOK, 128>>>(projcat, 384, 0,   q_norm_w,  qlat, DLQ);
    rms_kernel<<<NTOK, 128>>>(projcat, 384, 256, kv_norm_w, kvn,  DLKV);

    // absorbed q -> latent-kv: [8192,256] x [2048,256]^T (rounded for attention)
    tgemm3<128,true,true><<<dim3(16, NTOK/128, 1), 256, gsm128>>>(
        qlat, DLQ, 0, wc, DLQ, 0, biasc, qkv, NH*DLKV, 0, DLQ);

    attn_tc<<<dim3(SQ/64, NH, BB), 128, asm_>>>(qkv, kvn, vlat);

    // per-head value projection: v[:, h*64:(h+1)*64] = vlat[:, h] @ wkvbv[h]^T
    tgemm3<64,true,false><<<dim3(1, NTOK/128, NH), 256, gsm64>>>(
        vlat, NH*DLKV, DLKV, wkvbv, DLKV, (size_t)NDV*DLKV, nullptr, vv, NH*NDV, NDV, DLKV);

    // out = v @ wo_w^T + wo_b: [8192,1024] x [1024,1024]^T
    tgemm3<128,false,true><<<dim3(8, NTOK/128, 1), 256, gsm128>>>(
        vv, NH*NDV, 0, worn, NH*NDV, 0, wo_b, out, DIM, 0, NH*NDV);
}